// round 11
// baseline (speedup 1.0000x reference)
#include <cuda_runtime.h>
#include <cstdint>

// ============================================================================
// Problem constants
// ============================================================================
#define M_DIM 4096
#define K_DIM 4096
#define S_DIM 2048
#define N_DIM 16384            // B*S = 8*2048

#define BM 128
#define BN 128
#define BK 32
#define K_ITERS (K_DIM / BK)   // 128
#define STAGES 3

#define THREADS 288            // 8 consumer warps (2m x 4n, warp tile 64x32) + 1 producer

// Stage: A 128x32 fp32 (16KB) + B 128x32 fp32 (16KB), packed 32 words/row
#define A_STAGE_BYTES 16384
#define B_STAGE_BYTES 16384
#define STAGE_BYTES   (A_STAGE_BYTES + B_STAGE_BYTES)   // 32768
#define SMEM_STAGE0   1024
#define SMEM_BYTES    (SMEM_STAGE0 + STAGES * STAGE_BYTES)  // 99328 -> 2 CTAs/SM

// mbarriers: full[s] at s*16, empty[s] at s*16+8
#define MB_FULL(s)  ((s) * 16)
#define MB_EMPTY(s) ((s) * 16 + 8)

// ============================================================================
// Scratch layout (device globals) — validated chunk layout.
//
// Blocked: g_W[kb][m][32], g_X[kb][n][32]  (kb = k/32, chunk = 128B row)
// Within a 32-word chunk, logical k index j (0..31) stored at word c:
//   kk = j>>3, jj = j&7
//   p  = jj<4 ? 2*jj : 2*(jj-4)+1          (pair perm: [k0,k4,k1,k5,...])
//   c  = ((kk ^ (row & 3)) << 3) | p       (XOR swizzle -> conflict-free LDS.64)
// ============================================================================
__device__ __align__(128) float g_W[(size_t)M_DIM * K_DIM];   // 64 MB
__device__ __align__(128) float g_X[(size_t)N_DIM * K_DIM];   // 256 MB

// ============================================================================
// Helpers
// ============================================================================
__device__ __forceinline__ float tf32_rna(float f) {
    float o;
    asm("cvt.rna.tf32.f32 %0, %1;" : "=f"(o) : "f"(f));
    return o;
}

__device__ __forceinline__ uint32_t smem_u32(const void* p) {
    uint32_t a;
    asm("{ .reg .u64 t; cvta.to.shared.u64 t, %1; cvt.u32.u64 %0, t; }"
        : "=r"(a) : "l"(p));
    return a;
}

__device__ __forceinline__ uint32_t elect_one_pred() {
    uint32_t pred;
    asm volatile(
        "{\n\t.reg .pred p;\n\telect.sync _|p, 0xFFFFFFFF;\n\tselp.b32 %0, 1, 0, p;\n\t}"
        : "=r"(pred));
    return pred;
}

// LDS.64 with compile-time immediate offset in the addressing mode.
template <int IMM>
__device__ __forceinline__ uint2 lds64i(uint32_t addr) {
    uint2 v;
    asm volatile("ld.shared.v2.u32 {%0,%1}, [%2+%3];"
                 : "=r"(v.x), "=r"(v.y) : "r"(addr), "n"(IMM));
    return v;
}

__device__ __forceinline__ void mma_tf32(float* c,
                                         uint32_t a0, uint32_t a1,
                                         uint32_t a2, uint32_t a3,
                                         uint32_t b0, uint32_t b1) {
    asm volatile(
        "mma.sync.aligned.m16n8k8.row.col.f32.tf32.tf32.f32 "
        "{%0,%1,%2,%3}, {%4,%5,%6,%7}, {%8,%9}, {%0,%1,%2,%3};"
        : "+f"(c[0]), "+f"(c[1]), "+f"(c[2]), "+f"(c[3])
        : "r"(a0), "r"(a1), "r"(a2), "r"(a3), "r"(b0), "r"(b1));
}

#define MBARRIER_INIT(mbar, count) \
    asm volatile("mbarrier.init.shared.b64 [%0], %1;" \
                 :: "r"((uint32_t)(mbar)), "r"((uint32_t)(count)) : "memory")

#define MBARRIER_ARRIVE(mbar) \
    asm volatile("mbarrier.arrive.shared.b64 _, [%0];" \
                 :: "r"((uint32_t)(mbar)) : "memory")

#define MBARRIER_EXPECT_TX(mbar, tx_bytes) \
    asm volatile("mbarrier.arrive.expect_tx.shared.b64 _, [%0], %1;" \
                 :: "r"((uint32_t)(mbar)), "r"((uint32_t)(tx_bytes)) : "memory")

#define MBARRIER_WAIT_PARITY(mbar, parity) do {                                   \
    uint32_t _mbar = (uint32_t)(mbar);                                            \
    uint32_t _par = (uint32_t)(parity);                                           \
    uint32_t _done;                                                               \
    asm volatile(                                                                 \
        "{\n\t.reg .pred p;\n\t"                                                  \
        "mbarrier.try_wait.parity.acquire.cta.shared::cta.b64 p, [%1], %2;\n\t"   \
        "selp.b32 %0, 1, 0, p;\n\t}"                                              \
        : "=r"(_done) : "r"(_mbar), "r"(_par) : "memory");                        \
    if (!_done) {                                                                 \
        asm volatile(                                                             \
            "{\n\t.reg .pred P1;\n\t"                                             \
            "WAIT_LOOP_%=:\n\t"                                                   \
            "mbarrier.try_wait.parity.acquire.cta.shared::cta.b64 P1, [%0], %1, 0x989680;\n\t" \
            "@P1 bra.uni WAIT_DONE_%=;\n\t"                                       \
            "bra.uni WAIT_LOOP_%=;\n\t"                                           \
            "WAIT_DONE_%=:\n\t}"                                                  \
            :: "r"(_mbar), "r"(_par) : "memory");                                 \
    }                                                                             \
} while (0)

#define MBARRIER_WAIT_PARITY_RELAXED(mbar, parity) do {                           \
    uint32_t _mbar = (uint32_t)(mbar);                                            \
    uint32_t _par = (uint32_t)(parity);                                           \
    uint32_t _done;                                                               \
    asm volatile(                                                                 \
        "{\n\t.reg .pred p;\n\t"                                                  \
        "mbarrier.try_wait.parity.relaxed.cta.shared::cta.b64 p, [%1], %2, 0x989680;\n\t" \
        "selp.b32 %0, 1, 0, p;\n\t}"                                              \
        : "=r"(_done) : "r"(_mbar), "r"(_par) : "memory");                        \
    if (!_done) {                                                                 \
        asm volatile(                                                             \
            "{\n\t.reg .pred P1;\n\t"                                             \
            "WAIT_LOOP_%=:\n\t"                                                   \
            "mbarrier.try_wait.parity.relaxed.cta.shared::cta.b64 P1, [%0], %1, 0x989680;\n\t" \
            "@P1 bra.uni WAIT_DONE_%=;\n\t"                                       \
            "bra.uni WAIT_LOOP_%=;\n\t"                                           \
            "WAIT_DONE_%=:\n\t}"                                                  \
            :: "r"(_mbar), "r"(_par) : "memory");                                 \
    }                                                                             \
} while (0)

#define BULK_G2S(dst_smem, src_gmem, nbytes, mbar)                                \
    asm volatile(                                                                 \
        "cp.async.bulk.shared::cta.global.mbarrier::complete_tx::bytes "          \
        "[%0], [%1], %2, [%3];"                                                   \
        :: "r"((uint32_t)(dst_smem)), "l"(src_gmem),                              \
           "r"((uint32_t)(nbytes)), "r"((uint32_t)(mbar)) : "memory")

// ============================================================================
// Pre-pass kernels (identical to validated R5)
// ============================================================================
__global__ void scatter_kernel(const float* __restrict__ vals,
                               const int* __restrict__ rows,
                               const int* __restrict__ cols, int nnz) {
    int i = blockIdx.x * blockDim.x + threadIdx.x;
    if (i < nnz) {
        int r = rows[i], c = cols[i];
        int kb = c >> 5, j = c & 31, kk = j >> 3, jj = j & 7;
        int p = (jj < 4) ? (jj << 1) : (((jj - 4) << 1) | 1);
        int cc = ((kk ^ (r & 3)) << 3) | p;
        atomicAdd(&g_W[(size_t)kb * (M_DIM * 32) + (size_t)r * 32 + cc], vals[i]);
    }
}

__global__ void round_w_kernel() {
    size_t n4 = (size_t)M_DIM * K_DIM / 4;
    float4* p = reinterpret_cast<float4*>(g_W);
    for (size_t i = blockIdx.x * blockDim.x + threadIdx.x; i < n4;
         i += (size_t)gridDim.x * blockDim.x) {
        float4 v = p[i];
        v.x = tf32_rna(v.x); v.y = tf32_rna(v.y);
        v.z = tf32_rna(v.z); v.w = tf32_rna(v.w);
        p[i] = v;
    }
}

__global__ void conv_x_kernel(const float* __restrict__ x) {
    size_t ngroups = (size_t)N_DIM * (K_DIM / 8);
    for (size_t i = blockIdx.x * blockDim.x + threadIdx.x; i < ngroups;
         i += (size_t)gridDim.x * blockDim.x) {
        int n  = (int)(i >> 9);            // K/8 = 512 groups per row
        int k8 = (int)(i & 511);
        int kb = k8 >> 2, kk = k8 & 3;
        const float4* src = reinterpret_cast<const float4*>(x + (size_t)n * K_DIM + k8 * 8);
        float4 v0 = src[0];                // k0..k3
        float4 v1 = src[1];                // k4..k7
        float4 o0, o1;
        o0.x = tf32_rna(v0.x); o0.y = tf32_rna(v1.x);   // k0,k4
        o0.z = tf32_rna(v0.y); o0.w = tf32_rna(v1.y);   // k1,k5
        o1.x = tf32_rna(v0.z); o1.y = tf32_rna(v1.z);   // k2,k6
        o1.z = tf32_rna(v0.w); o1.w = tf32_rna(v1.w);   // k3,k7
        float* dst = g_X + (size_t)kb * (N_DIM * 32) + (size_t)n * 32
                         + ((kk ^ (n & 3)) << 3);
        reinterpret_cast<float4*>(dst)[0] = o0;
        reinterpret_cast<float4*>(dst)[1] = o1;
    }
}

// ============================================================================
// Mainloop: warp tile 64(m) x 32(n) -> 4 mi x 4 ni of m16n8k8.
// Per kk: 8 A-loads + 4 B-loads, 16 MMAs. All SMEM offsets literal immediates.
// ============================================================================
#define MMA_ROWS(ni, bf)                                                        \
    mma_tf32(acc[0][ni], alo0.x, ahi0.x, alo0.y, ahi0.y, (bf).x, (bf).y);       \
    mma_tf32(acc[1][ni], alo1.x, ahi1.x, alo1.y, ahi1.y, (bf).x, (bf).y);       \
    mma_tf32(acc[2][ni], alo2.x, ahi2.x, alo2.y, ahi2.y, (bf).x, (bf).y);       \
    mma_tf32(acc[3][ni], alo3.x, ahi3.x, alo3.y, ahi3.y, (bf).x, (bf).y);

#define KK_BLOCK(S, KKI) do {                                                   \
    uint2 alo0 = lds64i<(S)*STAGE_BYTES +    0>(aAddr[KKI]);                    \
    uint2 ahi0 = lds64i<(S)*STAGE_BYTES + 1024>(aAddr[KKI]);                    \
    uint2 alo1 = lds64i<(S)*STAGE_BYTES + 2048>(aAddr[KKI]);                    \
    uint2 ahi1 = lds64i<(S)*STAGE_BYTES + 3072>(aAddr[KKI]);                    \
    uint2 alo2 = lds64i<(S)*STAGE_BYTES + 4096>(aAddr[KKI]);                    \
    uint2 ahi2 = lds64i<(S)*STAGE_BYTES + 5120>(aAddr[KKI]);                    \
    uint2 alo3 = lds64i<(S)*STAGE_BYTES + 6144>(aAddr[KKI]);                    \
    uint2 ahi3 = lds64i<(S)*STAGE_BYTES + 7168>(aAddr[KKI]);                    \
    uint2 b0 = lds64i<(S)*STAGE_BYTES +    0>(bAddr[KKI]);                      \
    uint2 b1 = lds64i<(S)*STAGE_BYTES + 1024>(bAddr[KKI]);                      \
    uint2 b2 = lds64i<(S)*STAGE_BYTES + 2048>(bAddr[KKI]);                      \
    uint2 b3 = lds64i<(S)*STAGE_BYTES + 3072>(bAddr[KKI]);                      \
    MMA_ROWS(0, b0); MMA_ROWS(1, b1); MMA_ROWS(2, b2); MMA_ROWS(3, b3);         \
} while (0)

#define CONSUME_STAGE(S) do {                                                   \
    MBARRIER_WAIT_PARITY(sbase + MB_FULL(S), ph);                               \
    KK_BLOCK(S, 0); KK_BLOCK(S, 1); KK_BLOCK(S, 2); KK_BLOCK(S, 3);             \
    __syncwarp();                                                               \
    if (lane == 0) MBARRIER_ARRIVE(sbase + MB_EMPTY(S));                        \
} while (0)

#define PRODUCE_STAGE(S, K) do {                                                \
    MBARRIER_WAIT_PARITY_RELAXED(sbase + MB_EMPTY(S), ph);                      \
    uint32_t full = sbase + MB_FULL(S);                                         \
    uint32_t dst  = sbase + SMEM_STAGE0 + (S) * STAGE_BYTES;                    \
    MBARRIER_EXPECT_TX(full, STAGE_BYTES);                                      \
    BULK_G2S(dst, Asrc0 + (size_t)(K) * (M_DIM * 32), A_STAGE_BYTES, full);     \
    BULK_G2S(dst + A_STAGE_BYTES, Bsrc0 + (size_t)(K) * (N_DIM * 32),           \
             B_STAGE_BYTES, full);                                              \
} while (0)

// ============================================================================
// Warp-specialized tf32 GEMM: out[b,m,s] = sum_k W[m,k]*X[n,k] + bias[s]
// CTA tile 128x128; 8 consumer warps + 1 producer; 2 CTAs per SM.
// ============================================================================
__global__ void __launch_bounds__(THREADS, 2) gemm_kernel(
    const float* __restrict__ bias, float* __restrict__ out)
{
    extern __shared__ uint32_t smem[];
    const uint32_t sbase = smem_u32(smem);

    const int tid  = threadIdx.x;
    const int wid  = tid >> 5;
    const int lane = tid & 31;

    // CTA tile mapping: bid = mt + 32*nt (wave covers all 32 m-tiles -> A reuse)
    const int mt = blockIdx.x & 31;
    const int nt = blockIdx.x >> 5;
    const int m0 = mt * BM;
    const int n0 = nt * BN;

    if (tid == 0) {
        #pragma unroll
        for (int s = 0; s < STAGES; s++) {
            MBARRIER_INIT(sbase + MB_FULL(s), 1);
            MBARRIER_INIT(sbase + MB_EMPTY(s), 8);
        }
    }
    __syncthreads();

    if (wid == 8) {
        // ------------------------- Producer warp -------------------------
        if (elect_one_pred()) {
            const float* Asrc0 = g_W + (size_t)m0 * 32;
            const float* Bsrc0 = g_X + (size_t)n0 * 32;
            int ph = 1;   // fresh barriers: parity-1 waits pass
            // 128 = 42 groups of 3 + 2 remainder
            for (int ko = 0; ko < 42; ko++) {
                const int k = ko * 3;
                PRODUCE_STAGE(0, k);
                PRODUCE_STAGE(1, k + 1);
                PRODUCE_STAGE(2, k + 2);
                ph ^= 1;
            }
            // remainder: k = 126, 127 on slots 0, 1 (ph back to 1 after 42 flips)
            PRODUCE_STAGE(0, 126);
            PRODUCE_STAGE(1, 127);
        }
        return;
    }

    // --------------------------- Consumer warps ---------------------------
    const int g  = lane >> 2;       // fragment row group 0..7
    const int t  = lane & 3;        // fragment col group 0..3
    const int gx = g & 3;           // XOR swizzle key
    const int wm = wid & 1;         // warp m index 0..1 (64 rows each)
    const int wn = wid >> 1;        // warp n index 0..3 (32 rows each)

    // Per-kk stage-0 base addresses; stage & mi/ni offsets are LDS immediates.
    uint32_t aAddr[4], bAddr[4];
    {
        const uint32_t aBase = sbase + SMEM_STAGE0
                             + (uint32_t)((wm * 64 + g) * 128 + t * 8);
        const uint32_t bBase = sbase + SMEM_STAGE0 + A_STAGE_BYTES
                             + (uint32_t)((wn * 32 + g) * 128 + t * 8);
        #pragma unroll
        for (int kk = 0; kk < 4; kk++) {
            const uint32_t kx = (uint32_t)(((kk ^ gx) & 3) << 5);
            aAddr[kk] = aBase + kx;
            bAddr[kk] = bBase + kx;
        }
    }

    float acc[4][4][4];
#pragma unroll
    for (int i = 0; i < 4; i++)
#pragma unroll
        for (int j = 0; j < 4; j++)
#pragma unroll
            for (int r = 0; r < 4; r++) acc[i][j][r] = 0.0f;

    int ph = 0;
    // 128 = 42 groups of 3 + 2 remainder (per-slot parity alternation holds)
    for (int ko = 0; ko < 42; ko++) {
        CONSUME_STAGE(0);
        CONSUME_STAGE(1);
        CONSUME_STAGE(2);
        ph ^= 1;
    }
    // remainder: slots 0, 1 at ph = 0 (42 flips from 0)
    CONSUME_STAGE(0);
    CONSUME_STAGE(1);

    // ------------------------------------------------------------------------
    // Epilogue: out[b, m, s] = acc + bias[s]; CTA tile lies in one batch
    // ------------------------------------------------------------------------
    const int b   = n0 >> 11;        // n0 / 2048
    const int s0c = n0 & 2047;
    float* obase = out + (size_t)b * M_DIM * S_DIM;

#pragma unroll
    for (int mi = 0; mi < 4; mi++) {
#pragma unroll
        for (int ni = 0; ni < 4; ni++) {
            int sl = s0c + wn * 32 + ni * 8 + 2 * t;
            float2 bv = *reinterpret_cast<const float2*>(bias + sl);
            int m = m0 + wm * 64 + mi * 16 + g;

            float2 v0;
            v0.x = acc[mi][ni][0] + bv.x;
            v0.y = acc[mi][ni][1] + bv.y;
            *reinterpret_cast<float2*>(obase + (size_t)m * S_DIM + sl) = v0;

            float2 v1;
            v1.x = acc[mi][ni][2] + bv.x;
            v1.y = acc[mi][ni][3] + bv.y;
            *reinterpret_cast<float2*>(obase + (size_t)(m + 8) * S_DIM + sl) = v1;
        }
    }
}

// ============================================================================
// Host launch
// ============================================================================
extern "C" void kernel_launch(void* const* d_in, const int* in_sizes, int n_in,
                              void* d_out, int out_size) {
    const float* x      = (const float*)d_in[0];
    const float* values = (const float*)d_in[1];
    const float* bias   = (const float*)d_in[2];
    const int* row_ids  = (const int*)d_in[3];
    const int* col_idx  = (const int*)d_in[4];
    int nnz = in_sizes[1];
    float* out = (float*)d_out;

    void* wptr = nullptr;
    cudaGetSymbolAddress(&wptr, g_W);

    // 1) zero W (each replay re-accumulates from zero)
    cudaMemsetAsync(wptr, 0, (size_t)M_DIM * K_DIM * sizeof(float));

    // 2) scatter-add COO values directly into blocked+swizzled W
    scatter_kernel<<<(nnz + 255) / 256, 256>>>(values, row_ids, col_idx, nnz);

    // 3) tf32-round W in place; build blocked+swizzled tf32 X
    round_w_kernel<<<2048, 256>>>();
    conv_x_kernel<<<4096, 256>>>(x);

    // 4) GEMM: grid = 32 m-tiles * 128 n-tiles, 2 CTAs per SM
    cudaFuncSetAttribute(gemm_kernel,
                         cudaFuncAttributeMaxDynamicSharedMemorySize,
                         SMEM_BYTES);
    gemm_kernel<<<(M_DIM / BM) * (N_DIM / BN), THREADS, SMEM_BYTES>>>(bias, out);
}

// round 12
// speedup vs baseline: 1.4556x; 1.4556x over previous
#include <cuda_runtime.h>
#include <cuda_fp16.h>
#include <cstdint>

// ============================================================================
// Problem constants
// ============================================================================
#define M_DIM 4096
#define K_DIM 4096
#define S_DIM 2048
#define N_DIM 16384            // B*S = 8*2048

#define BM 256
#define BN 128
#define BK 64                  // fp16: 64 k-elems = 128B per row chunk
#define K_ITERS (K_DIM / BK)   // 64
#define STAGES 4
#define K_OUTER (K_ITERS / STAGES)   // 16

#define THREADS 544            // 16 consumer warps (4m x 4n, warp tile 64x32) + 1 producer

// Stage: A 256x64 fp16 (32KB) + B 128x64 fp16 (16KB), packed 128B/row
#define A_STAGE_BYTES 32768
#define B_STAGE_BYTES 16384
#define STAGE_BYTES   (A_STAGE_BYTES + B_STAGE_BYTES)   // 49152
#define SMEM_STAGE0   1024
#define SMEM_BYTES    (SMEM_STAGE0 + STAGES * STAGE_BYTES)  // 197632

// mbarriers: full[s] at s*16, empty[s] at s*16+8
#define MB_FULL(s)  ((s) * 16)
#define MB_EMPTY(s) ((s) * 16 + 8)

// ============================================================================
// Scratch (device globals)
//
// g_W:  fp32 natural [m][k] — scatter-add target.
// g_Wh/g_Xh: fp16 blocked [kb][row][64]  (kb = k/64, chunk = 128B row).
// Within a 64-elem chunk, logical k index j (0..63) stored at half index:
//   kg = j>>4 (16-k group), w = (j&15)>>1 (b32 word), h = j&1
//   p  = 2*(w&3) + (w>>2)              (pair perm: word t adj word t+4)
//   gp = kg ^ (row & 3)                (XOR swizzle, 32B groups)
//   half_idx = (gp*8 + p)*2 + h
// => LDS.64 at [row*128 + gp*32 + t*8] yields b32 pair (word t, word t+4)
//    = k{2t,2t+1} and k{2t+8,2t+9}: exactly one m16n8k16 fragment pair.
// ============================================================================
__device__ __align__(128) float  g_W [(size_t)M_DIM * K_DIM];   // 64 MB
__device__ __align__(128) __half g_Wh[(size_t)M_DIM * K_DIM];   // 32 MB
__device__ __align__(128) __half g_Xh[(size_t)N_DIM * K_DIM];   // 128 MB

// ============================================================================
// Helpers
// ============================================================================
__device__ __forceinline__ uint32_t smem_u32(const void* p) {
    uint32_t a;
    asm("{ .reg .u64 t; cvta.to.shared.u64 t, %1; cvt.u32.u64 %0, t; }"
        : "=r"(a) : "l"(p));
    return a;
}

__device__ __forceinline__ uint32_t elect_one_pred() {
    uint32_t pred;
    asm volatile(
        "{\n\t.reg .pred p;\n\telect.sync _|p, 0xFFFFFFFF;\n\tselp.b32 %0, 1, 0, p;\n\t}"
        : "=r"(pred));
    return pred;
}

// LDS.64 with compile-time immediate offset in the addressing mode.
template <int IMM>
__device__ __forceinline__ uint2 lds64i(uint32_t addr) {
    uint2 v;
    asm volatile("ld.shared.v2.u32 {%0,%1}, [%2+%3];"
                 : "=r"(v.x), "=r"(v.y) : "r"(addr), "n"(IMM));
    return v;
}

// m16n8k16 fp16 MMA, fp32 accumulate.
__device__ __forceinline__ void mma_f16(float* c,
                                        uint32_t a0, uint32_t a1,
                                        uint32_t a2, uint32_t a3,
                                        uint32_t b0, uint32_t b1) {
    asm volatile(
        "mma.sync.aligned.m16n8k16.row.col.f32.f16.f16.f32 "
        "{%0,%1,%2,%3}, {%4,%5,%6,%7}, {%8,%9}, {%0,%1,%2,%3};"
        : "+f"(c[0]), "+f"(c[1]), "+f"(c[2]), "+f"(c[3])
        : "r"(a0), "r"(a1), "r"(a2), "r"(a3), "r"(b0), "r"(b1));
}

#define MBARRIER_INIT(mbar, count) \
    asm volatile("mbarrier.init.shared.b64 [%0], %1;" \
                 :: "r"((uint32_t)(mbar)), "r"((uint32_t)(count)) : "memory")

#define MBARRIER_ARRIVE(mbar) \
    asm volatile("mbarrier.arrive.shared.b64 _, [%0];" \
                 :: "r"((uint32_t)(mbar)) : "memory")

#define MBARRIER_EXPECT_TX(mbar, tx_bytes) \
    asm volatile("mbarrier.arrive.expect_tx.shared.b64 _, [%0], %1;" \
                 :: "r"((uint32_t)(mbar)), "r"((uint32_t)(tx_bytes)) : "memory")

#define MBARRIER_WAIT_PARITY(mbar, parity) do {                                   \
    uint32_t _mbar = (uint32_t)(mbar);                                            \
    uint32_t _par = (uint32_t)(parity);                                           \
    uint32_t _done;                                                               \
    asm volatile(                                                                 \
        "{\n\t.reg .pred p;\n\t"                                                  \
        "mbarrier.try_wait.parity.acquire.cta.shared::cta.b64 p, [%1], %2;\n\t"   \
        "selp.b32 %0, 1, 0, p;\n\t}"                                              \
        : "=r"(_done) : "r"(_mbar), "r"(_par) : "memory");                        \
    if (!_done) {                                                                 \
        asm volatile(                                                             \
            "{\n\t.reg .pred P1;\n\t"                                             \
            "WAIT_LOOP_%=:\n\t"                                                   \
            "mbarrier.try_wait.parity.acquire.cta.shared::cta.b64 P1, [%0], %1, 0x989680;\n\t" \
            "@P1 bra.uni WAIT_DONE_%=;\n\t"                                       \
            "bra.uni WAIT_LOOP_%=;\n\t"                                           \
            "WAIT_DONE_%=:\n\t}"                                                  \
            :: "r"(_mbar), "r"(_par) : "memory");                                 \
    }                                                                             \
} while (0)

#define MBARRIER_WAIT_PARITY_RELAXED(mbar, parity) do {                           \
    uint32_t _mbar = (uint32_t)(mbar);                                            \
    uint32_t _par = (uint32_t)(parity);                                           \
    uint32_t _done;                                                               \
    asm volatile(                                                                 \
        "{\n\t.reg .pred p;\n\t"                                                  \
        "mbarrier.try_wait.parity.relaxed.cta.shared::cta.b64 p, [%1], %2, 0x989680;\n\t" \
        "selp.b32 %0, 1, 0, p;\n\t}"                                              \
        : "=r"(_done) : "r"(_mbar), "r"(_par) : "memory");                        \
    if (!_done) {                                                                 \
        asm volatile(                                                             \
            "{\n\t.reg .pred P1;\n\t"                                             \
            "WAIT_LOOP_%=:\n\t"                                                   \
            "mbarrier.try_wait.parity.relaxed.cta.shared::cta.b64 P1, [%0], %1, 0x989680;\n\t" \
            "@P1 bra.uni WAIT_DONE_%=;\n\t"                                       \
            "bra.uni WAIT_LOOP_%=;\n\t"                                           \
            "WAIT_DONE_%=:\n\t}"                                                  \
            :: "r"(_mbar), "r"(_par) : "memory");                                 \
    }                                                                             \
} while (0)

#define BULK_G2S(dst_smem, src_gmem, nbytes, mbar)                                \
    asm volatile(                                                                 \
        "cp.async.bulk.shared::cta.global.mbarrier::complete_tx::bytes "          \
        "[%0], [%1], %2, [%3];"                                                   \
        :: "r"((uint32_t)(dst_smem)), "l"(src_gmem),                              \
           "r"((uint32_t)(nbytes)), "r"((uint32_t)(mbar)) : "memory")

// half index inside a 64-elem chunk for logical k-offset j in row `row`.
__device__ __forceinline__ int chunk_half(int row, int j) {
    int kg = j >> 4, w = (j & 15) >> 1, h = j & 1;
    int p = 2 * (w & 3) + (w >> 2);
    int gp = kg ^ (row & 3);
    return (gp * 8 + p) * 2 + h;
}

// ============================================================================
// Pre-pass kernels
// ============================================================================
__global__ void scatter_kernel(const float* __restrict__ vals,
                               const int* __restrict__ rows,
                               const int* __restrict__ cols, int nnz) {
    int i = blockIdx.x * blockDim.x + threadIdx.x;
    if (i < nnz) {
        atomicAdd(&g_W[(size_t)rows[i] * K_DIM + cols[i]], vals[i]);
    }
}

// g_W (fp32 natural) -> g_Wh (fp16 blocked+permuted). One thread per chunk.
__global__ void conv_w_kernel() {
    int idx = blockIdx.x * blockDim.x + threadIdx.x;      // M*K/64 = 262144
    if (idx >= M_DIM * (K_DIM / BK)) return;
    int m  = idx >> 6;                                    // K/64 = 64 chunks/row
    int kb = idx & 63;
    const float* src = g_W + (size_t)m * K_DIM + kb * BK;
    __half o[BK];
    #pragma unroll
    for (int j = 0; j < BK; j++) {
        o[chunk_half(m, j)] = __float2half_rn(src[j]);
    }
    uint4* dst = reinterpret_cast<uint4*>(
        g_Wh + (size_t)kb * (M_DIM * BK) + (size_t)m * BK);
    const uint4* os = reinterpret_cast<const uint4*>(o);
    #pragma unroll
    for (int q = 0; q < 8; q++) dst[q] = os[q];
}

// x (fp32 natural) -> g_Xh (fp16 blocked+permuted). One thread per chunk.
__global__ void conv_x_kernel(const float* __restrict__ x) {
    int idx = blockIdx.x * blockDim.x + threadIdx.x;      // N*K/64 = 1048576
    if (idx >= N_DIM * (K_DIM / BK)) return;
    int n  = idx >> 6;
    int kb = idx & 63;
    const float* src = x + (size_t)n * K_DIM + kb * BK;
    __half o[BK];
    #pragma unroll
    for (int j = 0; j < BK; j++) {
        o[chunk_half(n, j)] = __float2half_rn(src[j]);
    }
    uint4* dst = reinterpret_cast<uint4*>(
        g_Xh + (size_t)kb * (N_DIM * BK) + (size_t)n * BK);
    const uint4* os = reinterpret_cast<const uint4*>(o);
    #pragma unroll
    for (int q = 0; q < 8; q++) dst[q] = os[q];
}

// ============================================================================
// Mainloop: warp tile 64(m) x 32(n), m16n8k16 -> 4 mi x 4 ni per kstep,
// 4 ksteps of K=16 per k-iter (BK=64).
// Per kstep: 8 A LDS.64 + 4 B LDS.64, 16 MMAs. Offsets are literal immediates.
// A LDS.64 -> (a_lo, a_hi) = k{2t,2t+1} / k{2t+8,2t+9} for one row.
// ============================================================================
#define MMA_ROWS(ni, bf)                                                        \
    mma_f16(acc[0][ni], a0[0].x, a1[0].x, a0[0].y, a1[0].y, (bf).x, (bf).y);    \
    mma_f16(acc[1][ni], a0[1].x, a1[1].x, a0[1].y, a1[1].y, (bf).x, (bf).y);    \
    mma_f16(acc[2][ni], a0[2].x, a1[2].x, a0[2].y, a1[2].y, (bf).x, (bf).y);    \
    mma_f16(acc[3][ni], a0[3].x, a1[3].x, a0[3].y, a1[3].y, (bf).x, (bf).y);

#define KSTEP(S, KS) do {                                                       \
    uint2 a0[4], a1[4];                                                         \
    a0[0] = lds64i<(S)*STAGE_BYTES +    0>(aAddr[KS]);                          \
    a1[0] = lds64i<(S)*STAGE_BYTES + 1024>(aAddr[KS]);                          \
    a0[1] = lds64i<(S)*STAGE_BYTES + 2048>(aAddr[KS]);                          \
    a1[1] = lds64i<(S)*STAGE_BYTES + 3072>(aAddr[KS]);                          \
    a0[2] = lds64i<(S)*STAGE_BYTES + 4096>(aAddr[KS]);                          \
    a1[2] = lds64i<(S)*STAGE_BYTES + 5120>(aAddr[KS]);                          \
    a0[3] = lds64i<(S)*STAGE_BYTES + 6144>(aAddr[KS]);                          \
    a1[3] = lds64i<(S)*STAGE_BYTES + 7168>(aAddr[KS]);                          \
    uint2 b0 = lds64i<(S)*STAGE_BYTES +    0>(bAddr[KS]);                       \
    uint2 b1 = lds64i<(S)*STAGE_BYTES + 1024>(bAddr[KS]);                       \
    uint2 b2 = lds64i<(S)*STAGE_BYTES + 2048>(bAddr[KS]);                       \
    uint2 b3 = lds64i<(S)*STAGE_BYTES + 3072>(bAddr[KS]);                       \
    MMA_ROWS(0, b0); MMA_ROWS(1, b1); MMA_ROWS(2, b2); MMA_ROWS(3, b3);         \
} while (0)

#define CONSUME_STAGE(S) do {                                                   \
    MBARRIER_WAIT_PARITY(sbase + MB_FULL(S), ph);                               \
    KSTEP(S, 0); KSTEP(S, 1); KSTEP(S, 2); KSTEP(S, 3);                         \
    __syncwarp();                                                               \
    if (lane == 0) MBARRIER_ARRIVE(sbase + MB_EMPTY(S));                        \
} while (0)

// ============================================================================
// Warp-specialized fp16 GEMM: out[b,m,s] = sum_k W[m,k]*X[n,k] + bias[s]
// CTA tile 256x128; 16 consumer warps (4 per SMSP) + 1 producer.
// ============================================================================
__global__ void __launch_bounds__(THREADS, 1) gemm_kernel(
    const float* __restrict__ bias, float* __restrict__ out)
{
    extern __shared__ uint32_t smem[];
    const uint32_t sbase = smem_u32(smem);

    const int tid  = threadIdx.x;
    const int wid  = tid >> 5;
    const int lane = tid & 31;

    // CTA tile mapping: bid = mt + 16*nt (wave covers all 16 m-tiles -> A reuse)
    const int mt = blockIdx.x & 15;
    const int nt = blockIdx.x >> 4;
    const int m0 = mt * BM;
    const int n0 = nt * BN;

    if (tid == 0) {
        #pragma unroll
        for (int s = 0; s < STAGES; s++) {
            MBARRIER_INIT(sbase + MB_FULL(s), 1);
            MBARRIER_INIT(sbase + MB_EMPTY(s), 16);
        }
    }
    __syncthreads();

    if (wid == 16) {
        // ------------------------- Producer warp -------------------------
        if (elect_one_pred()) {
            const __half* Asrc0 = g_Wh + (size_t)m0 * BK;
            const __half* Bsrc0 = g_Xh + (size_t)n0 * BK;
            int ph = 1;   // fresh barriers: parity-1 waits pass
            for (int ko = 0; ko < K_OUTER; ko++) {
                #pragma unroll
                for (int s = 0; s < STAGES; s++) {
                    const int k = ko * STAGES + s;
                    MBARRIER_WAIT_PARITY_RELAXED(sbase + MB_EMPTY(s), ph);
                    uint32_t full = sbase + MB_FULL(s);
                    uint32_t dst  = sbase + SMEM_STAGE0 + s * STAGE_BYTES;
                    MBARRIER_EXPECT_TX(full, STAGE_BYTES);
                    BULK_G2S(dst, Asrc0 + (size_t)k * (M_DIM * BK),
                             A_STAGE_BYTES, full);
                    BULK_G2S(dst + A_STAGE_BYTES, Bsrc0 + (size_t)k * (N_DIM * BK),
                             B_STAGE_BYTES, full);
                }
                ph ^= 1;
            }
        }
        return;
    }

    // --------------------------- Consumer warps ---------------------------
    const int g  = lane >> 2;       // fragment row group 0..7
    const int t  = lane & 3;        // fragment k-word group 0..3
    const int gx = g & 3;           // XOR swizzle key
    const int wm = wid & 3;         // warp m index 0..3 (64 rows each)
    const int wn = wid >> 2;        // warp n index 0..3 (32 rows each)

    // Per-kstep stage-0 base addresses; stage & mi/ni offsets = LDS immediates.
    uint32_t aAddr[4], bAddr[4];
    {
        const uint32_t aBase = sbase + SMEM_STAGE0
                             + (uint32_t)((wm * 64 + g) * 128 + t * 8);
        const uint32_t bBase = sbase + SMEM_STAGE0 + A_STAGE_BYTES
                             + (uint32_t)((wn * 32 + g) * 128 + t * 8);
        #pragma unroll
        for (int ks = 0; ks < 4; ks++) {
            const uint32_t kx = (uint32_t)(((ks ^ gx) & 3) << 5);   // 32B groups
            aAddr[ks] = aBase + kx;
            bAddr[ks] = bBase + kx;
        }
    }

    float acc[4][4][4];
#pragma unroll
    for (int i = 0; i < 4; i++)
#pragma unroll
        for (int j = 0; j < 4; j++)
#pragma unroll
            for (int r = 0; r < 4; r++) acc[i][j][r] = 0.0f;

    int ph = 0;
    for (int ko = 0; ko < K_OUTER; ko++) {
        CONSUME_STAGE(0);
        CONSUME_STAGE(1);
        CONSUME_STAGE(2);
        CONSUME_STAGE(3);
        ph ^= 1;
    }

    // ------------------------------------------------------------------------
    // Epilogue: out[b, m, s] = acc + bias[s]; CTA tile lies in one batch
    // m16n8k16 accum layout == m16n8k8: c0,c1 row g cols 2t,2t+1; c2,c3 row g+8
    // ------------------------------------------------------------------------
    const int b   = n0 >> 11;        // n0 / 2048
    const int s0c = n0 & 2047;
    float* obase = out + (size_t)b * M_DIM * S_DIM;

#pragma unroll
    for (int mi = 0; mi < 4; mi++) {
#pragma unroll
        for (int ni = 0; ni < 4; ni++) {
            int sl = s0c + wn * 32 + ni * 8 + 2 * t;
            float2 bv = *reinterpret_cast<const float2*>(bias + sl);
            int m = m0 + wm * 64 + mi * 16 + g;

            float2 v0;
            v0.x = acc[mi][ni][0] + bv.x;
            v0.y = acc[mi][ni][1] + bv.y;
            *reinterpret_cast<float2*>(obase + (size_t)m * S_DIM + sl) = v0;

            float2 v1;
            v1.x = acc[mi][ni][2] + bv.x;
            v1.y = acc[mi][ni][3] + bv.y;
            *reinterpret_cast<float2*>(obase + (size_t)(m + 8) * S_DIM + sl) = v1;
        }
    }
}

// ============================================================================
// Host launch
// ============================================================================
extern "C" void kernel_launch(void* const* d_in, const int* in_sizes, int n_in,
                              void* d_out, int out_size) {
    const float* x      = (const float*)d_in[0];
    const float* values = (const float*)d_in[1];
    const float* bias   = (const float*)d_in[2];
    const int* row_ids  = (const int*)d_in[3];
    const int* col_idx  = (const int*)d_in[4];
    int nnz = in_sizes[1];
    float* out = (float*)d_out;

    void* wptr = nullptr;
    cudaGetSymbolAddress(&wptr, g_W);

    // 1) zero fp32 W (each replay re-accumulates from zero)
    cudaMemsetAsync(wptr, 0, (size_t)M_DIM * K_DIM * sizeof(float));

    // 2) scatter-add COO values into natural fp32 W
    scatter_kernel<<<(nnz + 255) / 256, 256>>>(values, row_ids, col_idx, nnz);

    // 3) convert W and x to fp16 blocked+permuted staging buffers
    conv_w_kernel<<<(M_DIM * (K_DIM / BK) + 255) / 256, 256>>>();
    conv_x_kernel<<<(N_DIM * (K_DIM / BK) + 255) / 256, 256>>>(x);

    // 4) GEMM: grid = 16 m-tiles * 128 n-tiles
    cudaFuncSetAttribute(gemm_kernel,
                         cudaFuncAttributeMaxDynamicSharedMemorySize,
                         SMEM_BYTES);
    gemm_kernel<<<(M_DIM / BM) * (N_DIM / BN), THREADS, SMEM_BYTES>>>(bias, out);
}

// round 13
// speedup vs baseline: 2.3624x; 1.6230x over previous
#include <cuda_runtime.h>
#include <cuda_fp16.h>
#include <cstdint>

// ============================================================================
// Problem constants
// ============================================================================
#define M_DIM 4096
#define K_DIM 4096
#define S_DIM 2048
#define N_DIM 16384            // B*S = 8*2048

#define BM 256
#define BN 128
#define BK 64                  // fp16: 64 k-elems = 128B per row chunk
#define K_ITERS (K_DIM / BK)   // 64
#define STAGES 4
#define K_OUTER (K_ITERS / STAGES)   // 16

#define THREADS 512            // 16 warps, all consumers; warp0-lane0 also produces

// Stage: A 256x64 fp16 (32KB) + B 128x64 fp16 (16KB), packed 128B/row
#define A_STAGE_BYTES 32768
#define B_STAGE_BYTES 16384
#define STAGE_BYTES   (A_STAGE_BYTES + B_STAGE_BYTES)   // 49152
#define SMEM_STAGE0   1024
#define SMEM_BYTES    (SMEM_STAGE0 + STAGES * STAGE_BYTES)  // 197632

// mbarriers: full[s] at s*16, empty[s] at s*16+8
#define MB_FULL(s)  ((s) * 16)
#define MB_EMPTY(s) ((s) * 16 + 8)

// ============================================================================
// Scratch (device globals)
//
// g_W:  fp32 natural [m][k] — scatter-add target.
// g_Wh/g_Xh: fp16 blocked [kb][row][64]  (kb = k/64, chunk = 128B row).
// Within a 64-half chunk, logical k index j (0..63) stored at half index:
//   l = j>>3 (16B granule 0..7), stored granule = l ^ (row & 7)
//   half_idx = (l ^ (row&7))*8 + (j&7)
// => ldmatrix tiles (8 consecutive rows x one logical granule) hit 8 distinct
//    stored granules -> conflict-free.
// ============================================================================
__device__ __align__(128) float  g_W [(size_t)M_DIM * K_DIM];   // 64 MB
__device__ __align__(128) __half g_Wh[(size_t)M_DIM * K_DIM];   // 32 MB
__device__ __align__(128) __half g_Xh[(size_t)N_DIM * K_DIM];   // 128 MB

// ============================================================================
// Helpers
// ============================================================================
__device__ __forceinline__ uint32_t smem_u32(const void* p) {
    uint32_t a;
    asm("{ .reg .u64 t; cvta.to.shared.u64 t, %1; cvt.u32.u64 %0, t; }"
        : "=r"(a) : "l"(p));
    return a;
}

// ldmatrix x4 with compile-time immediate offset.
template <int IMM>
__device__ __forceinline__ void ldsm_x4(uint32_t* r, uint32_t addr) {
    asm volatile("ldmatrix.sync.aligned.m8n8.x4.shared.b16 {%0,%1,%2,%3}, [%4+%5];"
                 : "=r"(r[0]), "=r"(r[1]), "=r"(r[2]), "=r"(r[3])
                 : "r"(addr), "n"(IMM));
}

// m16n8k16 fp16 MMA, fp32 accumulate.
__device__ __forceinline__ void mma_f16(float* c,
                                        uint32_t a0, uint32_t a1,
                                        uint32_t a2, uint32_t a3,
                                        uint32_t b0, uint32_t b1) {
    asm volatile(
        "mma.sync.aligned.m16n8k16.row.col.f32.f16.f16.f32 "
        "{%0,%1,%2,%3}, {%4,%5,%6,%7}, {%8,%9}, {%0,%1,%2,%3};"
        : "+f"(c[0]), "+f"(c[1]), "+f"(c[2]), "+f"(c[3])
        : "r"(a0), "r"(a1), "r"(a2), "r"(a3), "r"(b0), "r"(b1));
}

#define MBARRIER_INIT(mbar, count) \
    asm volatile("mbarrier.init.shared.b64 [%0], %1;" \
                 :: "r"((uint32_t)(mbar)), "r"((uint32_t)(count)) : "memory")

#define MBARRIER_ARRIVE(mbar) \
    asm volatile("mbarrier.arrive.shared.b64 _, [%0];" \
                 :: "r"((uint32_t)(mbar)) : "memory")

#define MBARRIER_EXPECT_TX(mbar, tx_bytes) \
    asm volatile("mbarrier.arrive.expect_tx.shared.b64 _, [%0], %1;" \
                 :: "r"((uint32_t)(mbar)), "r"((uint32_t)(tx_bytes)) : "memory")

#define MBARRIER_WAIT_PARITY(mbar, parity) do {                                   \
    uint32_t _mbar = (uint32_t)(mbar);                                            \
    uint32_t _par = (uint32_t)(parity);                                           \
    uint32_t _done;                                                               \
    asm volatile(                                                                 \
        "{\n\t.reg .pred p;\n\t"                                                  \
        "mbarrier.try_wait.parity.acquire.cta.shared::cta.b64 p, [%1], %2;\n\t"   \
        "selp.b32 %0, 1, 0, p;\n\t}"                                              \
        : "=r"(_done) : "r"(_mbar), "r"(_par) : "memory");                        \
    if (!_done) {                                                                 \
        asm volatile(                                                             \
            "{\n\t.reg .pred P1;\n\t"                                             \
            "WAIT_LOOP_%=:\n\t"                                                   \
            "mbarrier.try_wait.parity.acquire.cta.shared::cta.b64 P1, [%0], %1, 0x989680;\n\t" \
            "@P1 bra.uni WAIT_DONE_%=;\n\t"                                       \
            "bra.uni WAIT_LOOP_%=;\n\t"                                           \
            "WAIT_DONE_%=:\n\t}"                                                  \
            :: "r"(_mbar), "r"(_par) : "memory");                                 \
    }                                                                             \
} while (0)

#define MBARRIER_WAIT_PARITY_RELAXED(mbar, parity) do {                           \
    uint32_t _mbar = (uint32_t)(mbar);                                            \
    uint32_t _par = (uint32_t)(parity);                                           \
    uint32_t _done;                                                               \
    asm volatile(                                                                 \
        "{\n\t.reg .pred p;\n\t"                                                  \
        "mbarrier.try_wait.parity.relaxed.cta.shared::cta.b64 p, [%1], %2, 0x989680;\n\t" \
        "selp.b32 %0, 1, 0, p;\n\t}"                                              \
        : "=r"(_done) : "r"(_mbar), "r"(_par) : "memory");                        \
    if (!_done) {                                                                 \
        asm volatile(                                                             \
            "{\n\t.reg .pred P1;\n\t"                                             \
            "WAIT_LOOP_%=:\n\t"                                                   \
            "mbarrier.try_wait.parity.relaxed.cta.shared::cta.b64 P1, [%0], %1, 0x989680;\n\t" \
            "@P1 bra.uni WAIT_DONE_%=;\n\t"                                       \
            "bra.uni WAIT_LOOP_%=;\n\t"                                           \
            "WAIT_DONE_%=:\n\t}"                                                  \
            :: "r"(_mbar), "r"(_par) : "memory");                                 \
    }                                                                             \
} while (0)

#define BULK_G2S(dst_smem, src_gmem, nbytes, mbar)                                \
    asm volatile(                                                                 \
        "cp.async.bulk.shared::cta.global.mbarrier::complete_tx::bytes "          \
        "[%0], [%1], %2, [%3];"                                                   \
        :: "r"((uint32_t)(dst_smem)), "l"(src_gmem),                              \
           "r"((uint32_t)(nbytes)), "r"((uint32_t)(mbar)) : "memory")

// half index inside a 64-half chunk for logical k-offset j in row `row`.
__device__ __forceinline__ int chunk_half(int row, int j) {
    int l = j >> 3;
    return ((l ^ (row & 7)) << 3) | (j & 7);
}

// ============================================================================
// Pre-pass kernels
// ============================================================================
__global__ void scatter_kernel(const float* __restrict__ vals,
                               const int* __restrict__ rows,
                               const int* __restrict__ cols, int nnz) {
    int i = blockIdx.x * blockDim.x + threadIdx.x;
    if (i < nnz) {
        atomicAdd(&g_W[(size_t)rows[i] * K_DIM + cols[i]], vals[i]);
    }
}

// g_W (fp32 natural) -> g_Wh (fp16 blocked + granule-XOR). One thread/chunk.
__global__ void conv_w_kernel() {
    int idx = blockIdx.x * blockDim.x + threadIdx.x;      // M*K/64 = 262144
    if (idx >= M_DIM * (K_DIM / BK)) return;
    int m  = idx >> 6;                                    // 64 chunks per row
    int kb = idx & 63;
    const float* src = g_W + (size_t)m * K_DIM + kb * BK;
    __half o[BK];
    #pragma unroll
    for (int j = 0; j < BK; j++) {
        o[chunk_half(m, j)] = __float2half_rn(src[j]);
    }
    uint4* dst = reinterpret_cast<uint4*>(
        g_Wh + (size_t)kb * (M_DIM * BK) + (size_t)m * BK);
    const uint4* os = reinterpret_cast<const uint4*>(o);
    #pragma unroll
    for (int q = 0; q < 8; q++) dst[q] = os[q];
}

// x (fp32 natural) -> g_Xh (fp16 blocked + granule-XOR). One thread/chunk.
__global__ void conv_x_kernel(const float* __restrict__ x) {
    int idx = blockIdx.x * blockDim.x + threadIdx.x;      // N*K/64 = 1048576
    if (idx >= N_DIM * (K_DIM / BK)) return;
    int n  = idx >> 6;
    int kb = idx & 63;
    const float* src = x + (size_t)n * K_DIM + kb * BK;
    __half o[BK];
    #pragma unroll
    for (int j = 0; j < BK; j++) {
        o[chunk_half(n, j)] = __float2half_rn(src[j]);
    }
    uint4* dst = reinterpret_cast<uint4*>(
        g_Xh + (size_t)kb * (N_DIM * BK) + (size_t)n * BK);
    const uint4* os = reinterpret_cast<const uint4*>(o);
    #pragma unroll
    for (int q = 0; q < 8; q++) dst[q] = os[q];
}

// ============================================================================
// Mainloop: warp tile 64(m) x 32(n), m16n8k16, 4 ksteps (K=16) per k-iter.
// Per kstep: 4 A ldmatrix.x4 (one per mi) + 2 B ldmatrix.x4 (2 ni each),
// 16 MMAs. Stage & mi/ni offsets are literal immediates on LDSM.
// A x4 -> {a0,a1,a2,a3} fragment order; B x4 -> {b0,b1} for ni, ni+1.
// ============================================================================
#define KSTEP(S, KS) do {                                                       \
    uint32_t a[4][4], bb[8];                                                    \
    ldsm_x4<(S)*STAGE_BYTES +    0>(a[0], aAddr[KS]);                           \
    ldsm_x4<(S)*STAGE_BYTES + 2048>(a[1], aAddr[KS]);                           \
    ldsm_x4<(S)*STAGE_BYTES + 4096>(a[2], aAddr[KS]);                           \
    ldsm_x4<(S)*STAGE_BYTES + 6144>(a[3], aAddr[KS]);                           \
    ldsm_x4<(S)*STAGE_BYTES +    0>(bb,     bAddr[KS]);                         \
    ldsm_x4<(S)*STAGE_BYTES + 2048>(bb + 4, bAddr[KS]);                         \
    _Pragma("unroll")                                                           \
    for (int ni = 0; ni < 4; ni++) {                                            \
        _Pragma("unroll")                                                       \
        for (int mi = 0; mi < 4; mi++) {                                        \
            mma_f16(acc[mi][ni], a[mi][0], a[mi][1], a[mi][2], a[mi][3],        \
                    bb[ni * 2], bb[ni * 2 + 1]);                                \
        }                                                                       \
    }                                                                           \
} while (0)

#define CONSUME_STAGE(S) do {                                                   \
    MBARRIER_WAIT_PARITY(sbase + MB_FULL(S), ph);                               \
    KSTEP(S, 0); KSTEP(S, 1); KSTEP(S, 2); KSTEP(S, 3);                         \
    __syncwarp();                                                               \
    if (lane == 0) MBARRIER_ARRIVE(sbase + MB_EMPTY(S));                        \
    if (tid == 0 && ko < K_OUTER - 1) {                                         \
        /* refill this slot with k-iter (4*ko + S + 4) */                       \
        MBARRIER_WAIT_PARITY_RELAXED(sbase + MB_EMPTY(S), ph);                  \
        const int knext = 4 * ko + (S) + 4;                                     \
        uint32_t full = sbase + MB_FULL(S);                                     \
        uint32_t dst  = sbase + SMEM_STAGE0 + (S) * STAGE_BYTES;                \
        MBARRIER_EXPECT_TX(full, STAGE_BYTES);                                  \
        BULK_G2S(dst, Asrc0 + (size_t)knext * (M_DIM * BK),                     \
                 A_STAGE_BYTES, full);                                          \
        BULK_G2S(dst + A_STAGE_BYTES, Bsrc0 + (size_t)knext * (N_DIM * BK),     \
                 B_STAGE_BYTES, full);                                          \
    }                                                                           \
} while (0)

// ============================================================================
// fp16 GEMM: out[b,m,s] = sum_k W[m,k]*X[n,k] + bias[s],  n = b*2048 + s
// CTA tile 256x128; 16 warps (4 per SMSP), warp0-lane0 doubles as producer.
// ============================================================================
__global__ void __launch_bounds__(THREADS, 1) gemm_kernel(
    const float* __restrict__ bias, float* __restrict__ out)
{
    extern __shared__ uint32_t smem[];
    const uint32_t sbase = smem_u32(smem);

    const int tid  = threadIdx.x;
    const int wid  = tid >> 5;
    const int lane = tid & 31;

    // CTA tile mapping: bid = mt + 16*nt (wave covers all 16 m-tiles -> A reuse)
    const int mt = blockIdx.x & 15;
    const int nt = blockIdx.x >> 4;
    const int m0 = mt * BM;
    const int n0 = nt * BN;

    const __half* Asrc0 = g_Wh + (size_t)m0 * BK;
    const __half* Bsrc0 = g_Xh + (size_t)n0 * BK;

    if (tid == 0) {
        #pragma unroll
        for (int s = 0; s < STAGES; s++) {
            MBARRIER_INIT(sbase + MB_FULL(s), 1);
            MBARRIER_INIT(sbase + MB_EMPTY(s), 16);
        }
    }
    __syncthreads();

    // Prologue: fill all 4 stages (k = 0..3)
    if (tid == 0) {
        #pragma unroll
        for (int s = 0; s < STAGES; s++) {
            uint32_t full = sbase + MB_FULL(s);
            uint32_t dst  = sbase + SMEM_STAGE0 + s * STAGE_BYTES;
            MBARRIER_EXPECT_TX(full, STAGE_BYTES);
            BULK_G2S(dst, Asrc0 + (size_t)s * (M_DIM * BK), A_STAGE_BYTES, full);
            BULK_G2S(dst + A_STAGE_BYTES, Bsrc0 + (size_t)s * (N_DIM * BK),
                     B_STAGE_BYTES, full);
        }
    }

    // ------------------------- Fragment addressing -------------------------
    const int wm = wid & 3;         // warp m index 0..3 (64 rows each)
    const int wn = wid >> 2;        // warp n index 0..3 (32 rows each)
    const int l7 = lane & 7;        // XOR key == (stage row & 7) for all tiles

    // A ldmatrix lane row: lanes 0-15 -> rows 0-15 (k-lo), 16-31 -> rows (k-hi)
    const int rA = lane & 15;
    const int hA = lane >> 4;
    // B ldmatrix lane row: 0-7/8-15 -> rows of ni (k-lo/k-hi); 16-31 -> ni+1
    const int rB = (lane & 7) + ((lane & 16) >> 1);
    const int hB = (lane >> 3) & 1;

    uint32_t aAddr[4], bAddr[4];
    #pragma unroll
    for (int ks = 0; ks < 4; ks++) {
        aAddr[ks] = sbase + SMEM_STAGE0
                  + (uint32_t)((wm * 64 + rA) * 128)
                  + (uint32_t)(((2 * ks + hA) ^ l7) << 4);
        bAddr[ks] = sbase + SMEM_STAGE0 + A_STAGE_BYTES
                  + (uint32_t)((wn * 32 + rB) * 128)
                  + (uint32_t)(((2 * ks + hB) ^ l7) << 4);
    }

    float acc[4][4][4];
#pragma unroll
    for (int i = 0; i < 4; i++)
#pragma unroll
        for (int j = 0; j < 4; j++)
#pragma unroll
            for (int r = 0; r < 4; r++) acc[i][j][r] = 0.0f;

    for (int ko = 0; ko < K_OUTER; ko++) {
        const int ph = ko & 1;
        CONSUME_STAGE(0);
        CONSUME_STAGE(1);
        CONSUME_STAGE(2);
        CONSUME_STAGE(3);
    }

    // ------------------------------------------------------------------------
    // Epilogue: out[b, m, s] = acc + bias[s]; CTA tile lies in one batch
    // m16n8k16 accum: c0,c1 -> row g cols 2t,2t+1; c2,c3 -> row g+8
    // ------------------------------------------------------------------------
    const int g = lane >> 2;
    const int t = lane & 3;
    const int b   = n0 >> 11;        // n0 / 2048
    const int s0c = n0 & 2047;
    float* obase = out + (size_t)b * M_DIM * S_DIM;

#pragma unroll
    for (int mi = 0; mi < 4; mi++) {
#pragma unroll
        for (int ni = 0; ni < 4; ni++) {
            int sl = s0c + wn * 32 + ni * 8 + 2 * t;
            float2 bv = *reinterpret_cast<const float2*>(bias + sl);
            int m = m0 + wm * 64 + mi * 16 + g;

            float2 v0;
            v0.x = acc[mi][ni][0] + bv.x;
            v0.y = acc[mi][ni][1] + bv.y;
            *reinterpret_cast<float2*>(obase + (size_t)m * S_DIM + sl) = v0;

            float2 v1;
            v1.x = acc[mi][ni][2] + bv.x;
            v1.y = acc[mi][ni][3] + bv.y;
            *reinterpret_cast<float2*>(obase + (size_t)(m + 8) * S_DIM + sl) = v1;
        }
    }
}

// ============================================================================
// Host launch
// ============================================================================
extern "C" void kernel_launch(void* const* d_in, const int* in_sizes, int n_in,
                              void* d_out, int out_size) {
    const float* x      = (const float*)d_in[0];
    const float* values = (const float*)d_in[1];
    const float* bias   = (const float*)d_in[2];
    const int* row_ids  = (const int*)d_in[3];
    const int* col_idx  = (const int*)d_in[4];
    int nnz = in_sizes[1];
    float* out = (float*)d_out;

    void* wptr = nullptr;
    cudaGetSymbolAddress(&wptr, g_W);

    // 1) zero fp32 W (each replay re-accumulates from zero)
    cudaMemsetAsync(wptr, 0, (size_t)M_DIM * K_DIM * sizeof(float));

    // 2) scatter-add COO values into natural fp32 W
    scatter_kernel<<<(nnz + 255) / 256, 256>>>(values, row_ids, col_idx, nnz);

    // 3) convert W and x to fp16 blocked + granule-XOR staging buffers
    conv_w_kernel<<<(M_DIM * (K_DIM / BK) + 255) / 256, 256>>>();
    conv_x_kernel<<<(N_DIM * (K_DIM / BK) + 255) / 256, 256>>>(x);

    // 4) GEMM: grid = 16 m-tiles * 128 n-tiles
    cudaFuncSetAttribute(gemm_kernel,
                         cudaFuncAttributeMaxDynamicSharedMemorySize,
                         SMEM_BYTES);
    gemm_kernel<<<(M_DIM / BM) * (N_DIM / BN), THREADS, SMEM_BYTES>>>(bias, out);
}

// round 14
// speedup vs baseline: 2.8316x; 1.1986x over previous
#include <cuda_runtime.h>
#include <cuda_fp16.h>
#include <cstdint>

// ============================================================================
// Problem constants
// ============================================================================
#define M_DIM 4096
#define K_DIM 4096
#define S_DIM 2048
#define N_DIM 16384            // B*S = 8*2048

#define BM 256
#define BN 128
#define BK 64                  // fp16: 64 k-elems = 128B per row chunk
#define K_ITERS (K_DIM / BK)   // 64
#define STAGES 4
#define K_OUTER (K_ITERS / STAGES)   // 16

#define THREADS 512            // 16 warps, all consumers; warp0-lane0 also produces

// Stage: A 256x64 fp16 (32KB) + B 128x64 fp16 (16KB), packed 128B/row
#define A_STAGE_BYTES 32768
#define B_STAGE_BYTES 16384
#define STAGE_BYTES   (A_STAGE_BYTES + B_STAGE_BYTES)   // 49152
#define SMEM_STAGE0   1024
#define SMEM_BYTES    (SMEM_STAGE0 + STAGES * STAGE_BYTES)  // 197632

// mbarriers: full[s] at s*16, empty[s] at s*16+8
#define MB_FULL(s)  ((s) * 16)
#define MB_EMPTY(s) ((s) * 16 + 8)

// ============================================================================
// Scratch (device globals)
//
// g_W:  fp32 natural [m][k] — scatter-add target.
// g_Wh/g_Xh: fp16 blocked [kb][row][64]  (kb = k/64, chunk = 128B row).
// Within a 64-half chunk, logical k index j (0..63) stored at half index:
//   l = j>>3 (16B granule 0..7), stored granule = l ^ (row & 7)
//   half_idx = (l ^ (row&7))*8 + (j&7)
// => ldmatrix tiles (8 consecutive rows x one logical granule) hit 8 distinct
//    stored granules -> conflict-free.
// ============================================================================
__device__ __align__(128) float  g_W [(size_t)M_DIM * K_DIM];   // 64 MB
__device__ __align__(128) __half g_Wh[(size_t)M_DIM * K_DIM];   // 32 MB
__device__ __align__(128) __half g_Xh[(size_t)N_DIM * K_DIM];   // 128 MB

// ============================================================================
// Helpers
// ============================================================================
__device__ __forceinline__ uint32_t smem_u32(const void* p) {
    uint32_t a;
    asm("{ .reg .u64 t; cvta.to.shared.u64 t, %1; cvt.u32.u64 %0, t; }"
        : "=r"(a) : "l"(p));
    return a;
}

// ldmatrix x4 with compile-time immediate offset.
template <int IMM>
__device__ __forceinline__ void ldsm_x4(uint32_t* r, uint32_t addr) {
    asm volatile("ldmatrix.sync.aligned.m8n8.x4.shared.b16 {%0,%1,%2,%3}, [%4+%5];"
                 : "=r"(r[0]), "=r"(r[1]), "=r"(r[2]), "=r"(r[3])
                 : "r"(addr), "n"(IMM));
}

// m16n8k16 fp16 MMA, fp32 accumulate.
__device__ __forceinline__ void mma_f16(float* c,
                                        uint32_t a0, uint32_t a1,
                                        uint32_t a2, uint32_t a3,
                                        uint32_t b0, uint32_t b1) {
    asm volatile(
        "mma.sync.aligned.m16n8k16.row.col.f32.f16.f16.f32 "
        "{%0,%1,%2,%3}, {%4,%5,%6,%7}, {%8,%9}, {%0,%1,%2,%3};"
        : "+f"(c[0]), "+f"(c[1]), "+f"(c[2]), "+f"(c[3])
        : "r"(a0), "r"(a1), "r"(a2), "r"(a3), "r"(b0), "r"(b1));
}

#define MBARRIER_INIT(mbar, count) \
    asm volatile("mbarrier.init.shared.b64 [%0], %1;" \
                 :: "r"((uint32_t)(mbar)), "r"((uint32_t)(count)) : "memory")

#define MBARRIER_ARRIVE(mbar) \
    asm volatile("mbarrier.arrive.shared.b64 _, [%0];" \
                 :: "r"((uint32_t)(mbar)) : "memory")

#define MBARRIER_EXPECT_TX(mbar, tx_bytes) \
    asm volatile("mbarrier.arrive.expect_tx.shared.b64 _, [%0], %1;" \
                 :: "r"((uint32_t)(mbar)), "r"((uint32_t)(tx_bytes)) : "memory")

#define MBARRIER_WAIT_PARITY(mbar, parity) do {                                   \
    uint32_t _mbar = (uint32_t)(mbar);                                            \
    uint32_t _par = (uint32_t)(parity);                                           \
    uint32_t _done;                                                               \
    asm volatile(                                                                 \
        "{\n\t.reg .pred p;\n\t"                                                  \
        "mbarrier.try_wait.parity.acquire.cta.shared::cta.b64 p, [%1], %2;\n\t"   \
        "selp.b32 %0, 1, 0, p;\n\t}"                                              \
        : "=r"(_done) : "r"(_mbar), "r"(_par) : "memory");                        \
    if (!_done) {                                                                 \
        asm volatile(                                                             \
            "{\n\t.reg .pred P1;\n\t"                                             \
            "WAIT_LOOP_%=:\n\t"                                                   \
            "mbarrier.try_wait.parity.acquire.cta.shared::cta.b64 P1, [%0], %1, 0x989680;\n\t" \
            "@P1 bra.uni WAIT_DONE_%=;\n\t"                                       \
            "bra.uni WAIT_LOOP_%=;\n\t"                                           \
            "WAIT_DONE_%=:\n\t}"                                                  \
            :: "r"(_mbar), "r"(_par) : "memory");                                 \
    }                                                                             \
} while (0)

#define MBARRIER_WAIT_PARITY_RELAXED(mbar, parity) do {                           \
    uint32_t _mbar = (uint32_t)(mbar);                                            \
    uint32_t _par = (uint32_t)(parity);                                           \
    uint32_t _done;                                                               \
    asm volatile(                                                                 \
        "{\n\t.reg .pred p;\n\t"                                                  \
        "mbarrier.try_wait.parity.relaxed.cta.shared::cta.b64 p, [%1], %2, 0x989680;\n\t" \
        "selp.b32 %0, 1, 0, p;\n\t}"                                              \
        : "=r"(_done) : "r"(_mbar), "r"(_par) : "memory");                        \
    if (!_done) {                                                                 \
        asm volatile(                                                             \
            "{\n\t.reg .pred P1;\n\t"                                             \
            "WAIT_LOOP_%=:\n\t"                                                   \
            "mbarrier.try_wait.parity.relaxed.cta.shared::cta.b64 P1, [%0], %1, 0x989680;\n\t" \
            "@P1 bra.uni WAIT_DONE_%=;\n\t"                                       \
            "bra.uni WAIT_LOOP_%=;\n\t"                                           \
            "WAIT_DONE_%=:\n\t}"                                                  \
            :: "r"(_mbar), "r"(_par) : "memory");                                 \
    }                                                                             \
} while (0)

#define BULK_G2S(dst_smem, src_gmem, nbytes, mbar)                                \
    asm volatile(                                                                 \
        "cp.async.bulk.shared::cta.global.mbarrier::complete_tx::bytes "          \
        "[%0], [%1], %2, [%3];"                                                   \
        :: "r"((uint32_t)(dst_smem)), "l"(src_gmem),                              \
           "r"((uint32_t)(nbytes)), "r"((uint32_t)(mbar)) : "memory")

// ============================================================================
// Pre-pass kernels
// ============================================================================
__global__ void scatter_kernel(const float* __restrict__ vals,
                               const int* __restrict__ rows,
                               const int* __restrict__ cols, int nnz) {
    int i = blockIdx.x * blockDim.x + threadIdx.x;
    if (i < nnz) {
        atomicAdd(&g_W[(size_t)rows[i] * K_DIM + cols[i]], vals[i]);
    }
}

// Convert 8 fp32 -> one 16B fp16 granule (register-only, no local memory).
__device__ __forceinline__ uint4 cvt8(const float4* s) {
    float4 f0 = s[0];
    float4 f1 = s[1];
    __half2 h0 = __float22half2_rn(make_float2(f0.x, f0.y));
    __half2 h1 = __float22half2_rn(make_float2(f0.z, f0.w));
    __half2 h2 = __float22half2_rn(make_float2(f1.x, f1.y));
    __half2 h3 = __float22half2_rn(make_float2(f1.z, f1.w));
    uint4 o;
    o.x = *reinterpret_cast<uint32_t*>(&h0);
    o.y = *reinterpret_cast<uint32_t*>(&h1);
    o.z = *reinterpret_cast<uint32_t*>(&h2);
    o.w = *reinterpret_cast<uint32_t*>(&h3);
    return o;
}

// g_W (fp32 natural) -> g_Wh (fp16 blocked + granule-XOR).
// One thread per 16B output granule: stored granule g holds logical granule
// l = g ^ (row&7); read 32B of fp32 at src + l*8 floats, write 16B.
__global__ void conv_w_kernel() {
    int idx = blockIdx.x * blockDim.x + threadIdx.x;      // M*K/8 = 2097152
    if (idx >= M_DIM * (K_DIM / 8)) return;
    int g   = idx & 7;
    int m   = (idx >> 3) & (M_DIM - 1);
    int kb  = idx >> (3 + 12);                            // / (8 * M_DIM)
    int l   = g ^ (m & 7);
    const float4* src = reinterpret_cast<const float4*>(
        g_W + (size_t)m * K_DIM + kb * BK + l * 8);
    uint4* dst = reinterpret_cast<uint4*>(
        g_Wh + (size_t)kb * (M_DIM * BK) + (size_t)m * BK + g * 8);
    *dst = cvt8(src);
}

// x (fp32 natural) -> g_Xh (fp16 blocked + granule-XOR). Same scheme.
__global__ void conv_x_kernel(const float* __restrict__ x) {
    int idx = blockIdx.x * blockDim.x + threadIdx.x;      // N*K/8 = 8388608
    if (idx >= N_DIM * (K_DIM / 8)) return;
    int g   = idx & 7;
    int n   = (idx >> 3) & (N_DIM - 1);
    int kb  = idx >> (3 + 14);                            // / (8 * N_DIM)
    int l   = g ^ (n & 7);
    const float4* src = reinterpret_cast<const float4*>(
        x + (size_t)n * K_DIM + kb * BK + l * 8);
    uint4* dst = reinterpret_cast<uint4*>(
        g_Xh + (size_t)kb * (N_DIM * BK) + (size_t)n * BK + g * 8);
    *dst = cvt8(src);
}

// ============================================================================
// Mainloop: warp tile 64(m) x 32(n), m16n8k16, 4 ksteps (K=16) per k-iter.
// Per kstep: 4 A ldmatrix.x4 (one per mi) + 2 B ldmatrix.x4 (2 ni each),
// 16 MMAs. Stage & mi/ni offsets are literal immediates on LDSM.
// ============================================================================
#define KSTEP(S, KS) do {                                                       \
    uint32_t a[4][4], bb[8];                                                    \
    ldsm_x4<(S)*STAGE_BYTES +    0>(a[0], aAddr[KS]);                           \
    ldsm_x4<(S)*STAGE_BYTES + 2048>(a[1], aAddr[KS]);                           \
    ldsm_x4<(S)*STAGE_BYTES + 4096>(a[2], aAddr[KS]);                           \
    ldsm_x4<(S)*STAGE_BYTES + 6144>(a[3], aAddr[KS]);                           \
    ldsm_x4<(S)*STAGE_BYTES +    0>(bb,     bAddr[KS]);                         \
    ldsm_x4<(S)*STAGE_BYTES + 2048>(bb + 4, bAddr[KS]);                         \
    _Pragma("unroll")                                                           \
    for (int ni = 0; ni < 4; ni++) {                                            \
        _Pragma("unroll")                                                       \
        for (int mi = 0; mi < 4; mi++) {                                        \
            mma_f16(acc[mi][ni], a[mi][0], a[mi][1], a[mi][2], a[mi][3],        \
                    bb[ni * 2], bb[ni * 2 + 1]);                                \
        }                                                                       \
    }                                                                           \
} while (0)

#define CONSUME_STAGE(S) do {                                                   \
    MBARRIER_WAIT_PARITY(sbase + MB_FULL(S), ph);                               \
    KSTEP(S, 0); KSTEP(S, 1); KSTEP(S, 2); KSTEP(S, 3);                         \
    __syncwarp();                                                               \
    if (lane == 0) MBARRIER_ARRIVE(sbase + MB_EMPTY(S));                        \
    if (tid == 0 && ko < K_OUTER - 1) {                                         \
        /* refill this slot with k-iter (4*ko + S + 4) */                       \
        MBARRIER_WAIT_PARITY_RELAXED(sbase + MB_EMPTY(S), ph);                  \
        const int knext = 4 * ko + (S) + 4;                                     \
        uint32_t full = sbase + MB_FULL(S);                                     \
        uint32_t dst  = sbase + SMEM_STAGE0 + (S) * STAGE_BYTES;                \
        MBARRIER_EXPECT_TX(full, STAGE_BYTES);                                  \
        BULK_G2S(dst, Asrc0 + (size_t)knext * (M_DIM * BK),                     \
                 A_STAGE_BYTES, full);                                          \
        BULK_G2S(dst + A_STAGE_BYTES, Bsrc0 + (size_t)knext * (N_DIM * BK),     \
                 B_STAGE_BYTES, full);                                          \
    }                                                                           \
} while (0)

// ============================================================================
// fp16 GEMM: out[b,m,s] = sum_k W[m,k]*X[n,k] + bias[s],  n = b*2048 + s
// CTA tile 256x128; 16 warps (4 per SMSP), warp0-lane0 doubles as producer.
// ============================================================================
__global__ void __launch_bounds__(THREADS, 1) gemm_kernel(
    const float* __restrict__ bias, float* __restrict__ out)
{
    extern __shared__ uint32_t smem[];
    const uint32_t sbase = smem_u32(smem);

    const int tid  = threadIdx.x;
    const int wid  = tid >> 5;
    const int lane = tid & 31;

    // CTA tile mapping: bid = mt + 16*nt (wave covers all 16 m-tiles -> A reuse)
    const int mt = blockIdx.x & 15;
    const int nt = blockIdx.x >> 4;
    const int m0 = mt * BM;
    const int n0 = nt * BN;

    const __half* Asrc0 = g_Wh + (size_t)m0 * BK;
    const __half* Bsrc0 = g_Xh + (size_t)n0 * BK;

    if (tid == 0) {
        #pragma unroll
        for (int s = 0; s < STAGES; s++) {
            MBARRIER_INIT(sbase + MB_FULL(s), 1);
            MBARRIER_INIT(sbase + MB_EMPTY(s), 16);
        }
    }
    __syncthreads();

    // Prologue: fill all 4 stages (k = 0..3)
    if (tid == 0) {
        #pragma unroll
        for (int s = 0; s < STAGES; s++) {
            uint32_t full = sbase + MB_FULL(s);
            uint32_t dst  = sbase + SMEM_STAGE0 + s * STAGE_BYTES;
            MBARRIER_EXPECT_TX(full, STAGE_BYTES);
            BULK_G2S(dst, Asrc0 + (size_t)s * (M_DIM * BK), A_STAGE_BYTES, full);
            BULK_G2S(dst + A_STAGE_BYTES, Bsrc0 + (size_t)s * (N_DIM * BK),
                     B_STAGE_BYTES, full);
        }
    }

    // ------------------------- Fragment addressing -------------------------
    const int wm = wid & 3;         // warp m index 0..3 (64 rows each)
    const int wn = wid >> 2;        // warp n index 0..3 (32 rows each)
    const int l7 = lane & 7;        // XOR key == (stage row & 7) for all tiles

    // A ldmatrix lane row: lanes 0-15 -> rows 0-15 (k-lo), 16-31 -> rows (k-hi)
    const int rA = lane & 15;
    const int hA = lane >> 4;
    // B ldmatrix lane row: 0-7/8-15 -> rows of ni (k-lo/k-hi); 16-31 -> ni+1
    const int rB = (lane & 7) + ((lane & 16) >> 1);
    const int hB = (lane >> 3) & 1;

    uint32_t aAddr[4], bAddr[4];
    #pragma unroll
    for (int ks = 0; ks < 4; ks++) {
        aAddr[ks] = sbase + SMEM_STAGE0
                  + (uint32_t)((wm * 64 + rA) * 128)
                  + (uint32_t)(((2 * ks + hA) ^ l7) << 4);
        bAddr[ks] = sbase + SMEM_STAGE0 + A_STAGE_BYTES
                  + (uint32_t)((wn * 32 + rB) * 128)
                  + (uint32_t)(((2 * ks + hB) ^ l7) << 4);
    }

    float acc[4][4][4];
#pragma unroll
    for (int i = 0; i < 4; i++)
#pragma unroll
        for (int j = 0; j < 4; j++)
#pragma unroll
            for (int r = 0; r < 4; r++) acc[i][j][r] = 0.0f;

    for (int ko = 0; ko < K_OUTER; ko++) {
        const int ph = ko & 1;
        CONSUME_STAGE(0);
        CONSUME_STAGE(1);
        CONSUME_STAGE(2);
        CONSUME_STAGE(3);
    }

    // ------------------------------------------------------------------------
    // Epilogue: out[b, m, s] = acc + bias[s]; CTA tile lies in one batch
    // m16n8k16 accum: c0,c1 -> row g cols 2t,2t+1; c2,c3 -> row g+8
    // ------------------------------------------------------------------------
    const int g = lane >> 2;
    const int t = lane & 3;
    const int b   = n0 >> 11;        // n0 / 2048
    const int s0c = n0 & 2047;
    float* obase = out + (size_t)b * M_DIM * S_DIM;

#pragma unroll
    for (int mi = 0; mi < 4; mi++) {
#pragma unroll
        for (int ni = 0; ni < 4; ni++) {
            int sl = s0c + wn * 32 + ni * 8 + 2 * t;
            float2 bv = *reinterpret_cast<const float2*>(bias + sl);
            int m = m0 + wm * 64 + mi * 16 + g;

            float2 v0;
            v0.x = acc[mi][ni][0] + bv.x;
            v0.y = acc[mi][ni][1] + bv.y;
            *reinterpret_cast<float2*>(obase + (size_t)m * S_DIM + sl) = v0;

            float2 v1;
            v1.x = acc[mi][ni][2] + bv.x;
            v1.y = acc[mi][ni][3] + bv.y;
            *reinterpret_cast<float2*>(obase + (size_t)(m + 8) * S_DIM + sl) = v1;
        }
    }
}

// ============================================================================
// Host launch
// ============================================================================
extern "C" void kernel_launch(void* const* d_in, const int* in_sizes, int n_in,
                              void* d_out, int out_size) {
    const float* x      = (const float*)d_in[0];
    const float* values = (const float*)d_in[1];
    const float* bias   = (const float*)d_in[2];
    const int* row_ids  = (const int*)d_in[3];
    const int* col_idx  = (const int*)d_in[4];
    int nnz = in_sizes[1];
    float* out = (float*)d_out;

    void* wptr = nullptr;
    cudaGetSymbolAddress(&wptr, g_W);

    // 1) zero fp32 W (each replay re-accumulates from zero)
    cudaMemsetAsync(wptr, 0, (size_t)M_DIM * K_DIM * sizeof(float));

    // 2) scatter-add COO values into natural fp32 W
    scatter_kernel<<<(nnz + 255) / 256, 256>>>(values, row_ids, col_idx, nnz);

    // 3) convert W and x to fp16 blocked + granule-XOR staging (1 thr/granule)
    conv_w_kernel<<<(M_DIM * (K_DIM / 8) + 255) / 256, 256>>>();
    conv_x_kernel<<<(N_DIM * (K_DIM / 8) + 255) / 256, 256>>>(x);

    // 4) GEMM: grid = 16 m-tiles * 128 n-tiles
    cudaFuncSetAttribute(gemm_kernel,
                         cudaFuncAttributeMaxDynamicSharedMemorySize,
                         SMEM_BYTES);
    gemm_kernel<<<(M_DIM / BM) * (N_DIM / BN), THREADS, SMEM_BYTES>>>(bias, out);
}

// round 15
// speedup vs baseline: 2.8558x; 1.0085x over previous
#include <cuda_runtime.h>
#include <cuda_fp16.h>
#include <cstdint>

// ============================================================================
// Problem constants
// ============================================================================
#define M_DIM 4096
#define K_DIM 4096
#define S_DIM 2048
#define N_DIM 16384            // B*S = 8*2048

#define BM 256
#define BN 128
#define BK 64                  // fp16: 64 k-elems = 128B per row chunk
#define K_ITERS (K_DIM / BK)   // 64
#define STAGES 4
#define K_OUTER (K_ITERS / STAGES)   // 16

#define THREADS 512            // 16 warps, all consumers; warp0-lane0 also produces

// Stage: A 256x64 fp16 (32KB) + B 128x64 fp16 (16KB), packed 128B/row
#define A_STAGE_BYTES 32768
#define B_STAGE_BYTES 16384
#define STAGE_BYTES   (A_STAGE_BYTES + B_STAGE_BYTES)   // 49152
#define SMEM_STAGE0   1024
#define SMEM_BYTES    (SMEM_STAGE0 + STAGES * STAGE_BYTES)  // 197632

// mbarriers: full[s] at s*16, empty[s] at s*16+8
#define MB_FULL(s)  ((s) * 16)
#define MB_EMPTY(s) ((s) * 16 + 8)

// ============================================================================
// Scratch (device globals)
//
// g_Wh/g_Xh: fp16 blocked [kb][row][64]  (kb = k/64, chunk = 128B row).
// Within a 64-half chunk, logical k index j (0..63) stored at half index:
//   l = j>>3 (16B granule 0..7), stored granule = l ^ (row & 7)
//   half_idx = (l ^ (row&7))*8 + (j&7)
// => ldmatrix tiles (8 consecutive rows x one logical granule) hit 8 distinct
//    stored granules -> conflict-free.
// g_Wh is ALSO the scatter-add target (fp16 atomics, blocked address).
// ============================================================================
__device__ __align__(128) __half g_Wh[(size_t)M_DIM * K_DIM];   // 32 MB
__device__ __align__(128) __half g_Xh[(size_t)N_DIM * K_DIM];   // 128 MB

// ============================================================================
// Helpers
// ============================================================================
__device__ __forceinline__ uint32_t smem_u32(const void* p) {
    uint32_t a;
    asm("{ .reg .u64 t; cvta.to.shared.u64 t, %1; cvt.u32.u64 %0, t; }"
        : "=r"(a) : "l"(p));
    return a;
}

// ldmatrix x4 with compile-time immediate offset.
template <int IMM>
__device__ __forceinline__ void ldsm_x4(uint32_t* r, uint32_t addr) {
    asm volatile("ldmatrix.sync.aligned.m8n8.x4.shared.b16 {%0,%1,%2,%3}, [%4+%5];"
                 : "=r"(r[0]), "=r"(r[1]), "=r"(r[2]), "=r"(r[3])
                 : "r"(addr), "n"(IMM));
}

// m16n8k16 fp16 MMA, fp32 accumulate.
__device__ __forceinline__ void mma_f16(float* c,
                                        uint32_t a0, uint32_t a1,
                                        uint32_t a2, uint32_t a3,
                                        uint32_t b0, uint32_t b1) {
    asm volatile(
        "mma.sync.aligned.m16n8k16.row.col.f32.f16.f16.f32 "
        "{%0,%1,%2,%3}, {%4,%5,%6,%7}, {%8,%9}, {%0,%1,%2,%3};"
        : "+f"(c[0]), "+f"(c[1]), "+f"(c[2]), "+f"(c[3])
        : "r"(a0), "r"(a1), "r"(a2), "r"(a3), "r"(b0), "r"(b1));
}

#define MBARRIER_INIT(mbar, count) \
    asm volatile("mbarrier.init.shared.b64 [%0], %1;" \
                 :: "r"((uint32_t)(mbar)), "r"((uint32_t)(count)) : "memory")

#define MBARRIER_ARRIVE(mbar) \
    asm volatile("mbarrier.arrive.shared.b64 _, [%0];" \
                 :: "r"((uint32_t)(mbar)) : "memory")

#define MBARRIER_EXPECT_TX(mbar, tx_bytes) \
    asm volatile("mbarrier.arrive.expect_tx.shared.b64 _, [%0], %1;" \
                 :: "r"((uint32_t)(mbar)), "r"((uint32_t)(tx_bytes)) : "memory")

#define MBARRIER_WAIT_PARITY(mbar, parity) do {                                   \
    uint32_t _mbar = (uint32_t)(mbar);                                            \
    uint32_t _par = (uint32_t)(parity);                                           \
    uint32_t _done;                                                               \
    asm volatile(                                                                 \
        "{\n\t.reg .pred p;\n\t"                                                  \
        "mbarrier.try_wait.parity.acquire.cta.shared::cta.b64 p, [%1], %2;\n\t"   \
        "selp.b32 %0, 1, 0, p;\n\t}"                                              \
        : "=r"(_done) : "r"(_mbar), "r"(_par) : "memory");                        \
    if (!_done) {                                                                 \
        asm volatile(                                                             \
            "{\n\t.reg .pred P1;\n\t"                                             \
            "WAIT_LOOP_%=:\n\t"                                                   \
            "mbarrier.try_wait.parity.acquire.cta.shared::cta.b64 P1, [%0], %1, 0x989680;\n\t" \
            "@P1 bra.uni WAIT_DONE_%=;\n\t"                                       \
            "bra.uni WAIT_LOOP_%=;\n\t"                                           \
            "WAIT_DONE_%=:\n\t}"                                                  \
            :: "r"(_mbar), "r"(_par) : "memory");                                 \
    }                                                                             \
} while (0)

#define MBARRIER_WAIT_PARITY_RELAXED(mbar, parity) do {                           \
    uint32_t _mbar = (uint32_t)(mbar);                                            \
    uint32_t _par = (uint32_t)(parity);                                           \
    uint32_t _done;                                                               \
    asm volatile(                                                                 \
        "{\n\t.reg .pred p;\n\t"                                                  \
        "mbarrier.try_wait.parity.relaxed.cta.shared::cta.b64 p, [%1], %2, 0x989680;\n\t" \
        "selp.b32 %0, 1, 0, p;\n\t}"                                              \
        : "=r"(_done) : "r"(_mbar), "r"(_par) : "memory");                        \
    if (!_done) {                                                                 \
        asm volatile(                                                             \
            "{\n\t.reg .pred P1;\n\t"                                             \
            "WAIT_LOOP_%=:\n\t"                                                   \
            "mbarrier.try_wait.parity.relaxed.cta.shared::cta.b64 P1, [%0], %1, 0x989680;\n\t" \
            "@P1 bra.uni WAIT_DONE_%=;\n\t"                                       \
            "bra.uni WAIT_LOOP_%=;\n\t"                                           \
            "WAIT_DONE_%=:\n\t}"                                                  \
            :: "r"(_mbar), "r"(_par) : "memory");                                 \
    }                                                                             \
} while (0)

#define BULK_G2S(dst_smem, src_gmem, nbytes, mbar)                                \
    asm volatile(                                                                 \
        "cp.async.bulk.shared::cta.global.mbarrier::complete_tx::bytes "          \
        "[%0], [%1], %2, [%3];"                                                   \
        :: "r"((uint32_t)(dst_smem)), "l"(src_gmem),                              \
           "r"((uint32_t)(nbytes)), "r"((uint32_t)(mbar)) : "memory")

// ============================================================================
// Pre-pass kernels
// ============================================================================

// COO scatter-add DIRECTLY into the fp16 blocked+XOR layout.
__global__ void scatter_kernel(const float* __restrict__ vals,
                               const int* __restrict__ rows,
                               const int* __restrict__ cols, int nnz) {
    int i = blockIdx.x * blockDim.x + threadIdx.x;
    if (i < nnz) {
        int r  = rows[i], c = cols[i];
        int kb = c >> 6;                 // BK = 64
        int j  = c & 63;
        int l  = j >> 3;
        int g  = l ^ (r & 7);
        size_t off = (size_t)kb * (M_DIM * BK) + (size_t)r * BK + g * 8 + (j & 7);
        atomicAdd(&g_Wh[off], __float2half(vals[i]));
    }
}

// Convert 8 fp32 -> one 16B fp16 granule (register-only, no local memory).
__device__ __forceinline__ uint4 cvt8(const float4* s) {
    float4 f0 = s[0];
    float4 f1 = s[1];
    __half2 h0 = __float22half2_rn(make_float2(f0.x, f0.y));
    __half2 h1 = __float22half2_rn(make_float2(f0.z, f0.w));
    __half2 h2 = __float22half2_rn(make_float2(f1.x, f1.y));
    __half2 h3 = __float22half2_rn(make_float2(f1.z, f1.w));
    uint4 o;
    o.x = *reinterpret_cast<uint32_t*>(&h0);
    o.y = *reinterpret_cast<uint32_t*>(&h1);
    o.z = *reinterpret_cast<uint32_t*>(&h2);
    o.w = *reinterpret_cast<uint32_t*>(&h3);
    return o;
}

// x (fp32 natural) -> g_Xh (fp16 blocked + granule-XOR). One thread/granule.
__global__ void conv_x_kernel(const float* __restrict__ x) {
    int idx = blockIdx.x * blockDim.x + threadIdx.x;      // N*K/8 = 8388608
    if (idx >= N_DIM * (K_DIM / 8)) return;
    int g   = idx & 7;
    int n   = (idx >> 3) & (N_DIM - 1);
    int kb  = idx >> (3 + 14);                            // / (8 * N_DIM)
    int l   = g ^ (n & 7);
    const float4* src = reinterpret_cast<const float4*>(
        x + (size_t)n * K_DIM + kb * BK + l * 8);
    uint4* dst = reinterpret_cast<uint4*>(
        g_Xh + (size_t)kb * (N_DIM * BK) + (size_t)n * BK + g * 8);
    *dst = cvt8(src);
}

// ============================================================================
// Mainloop: warp tile 64(m) x 32(n), m16n8k16, 4 ksteps (K=16) per k-iter.
// Per kstep: 4 A ldmatrix.x4 (one per mi) + 2 B ldmatrix.x4 (2 ni each),
// 16 MMAs. Stage & mi/ni offsets are literal immediates on LDSM.
// ============================================================================
#define KSTEP(S, KS) do {                                                       \
    uint32_t a[4][4], bb[8];                                                    \
    ldsm_x4<(S)*STAGE_BYTES +    0>(a[0], aAddr[KS]);                           \
    ldsm_x4<(S)*STAGE_BYTES + 2048>(a[1], aAddr[KS]);                           \
    ldsm_x4<(S)*STAGE_BYTES + 4096>(a[2], aAddr[KS]);                           \
    ldsm_x4<(S)*STAGE_BYTES + 6144>(a[3], aAddr[KS]);                           \
    ldsm_x4<(S)*STAGE_BYTES +    0>(bb,     bAddr[KS]);                         \
    ldsm_x4<(S)*STAGE_BYTES + 2048>(bb + 4, bAddr[KS]);                         \
    _Pragma("unroll")                                                           \
    for (int ni = 0; ni < 4; ni++) {                                            \
        _Pragma("unroll")                                                       \
        for (int mi = 0; mi < 4; mi++) {                                        \
            mma_f16(acc[mi][ni], a[mi][0], a[mi][1], a[mi][2], a[mi][3],        \
                    bb[ni * 2], bb[ni * 2 + 1]);                                \
        }                                                                       \
    }                                                                           \
} while (0)

#define CONSUME_STAGE(S) do {                                                   \
    MBARRIER_WAIT_PARITY(sbase + MB_FULL(S), ph);                               \
    KSTEP(S, 0); KSTEP(S, 1); KSTEP(S, 2); KSTEP(S, 3);                         \
    __syncwarp();                                                               \
    if (lane == 0) MBARRIER_ARRIVE(sbase + MB_EMPTY(S));                        \
    if (tid == 0 && ko < K_OUTER - 1) {                                         \
        /* refill this slot with k-iter (4*ko + S + 4) */                       \
        MBARRIER_WAIT_PARITY_RELAXED(sbase + MB_EMPTY(S), ph);                  \
        const int knext = 4 * ko + (S) + 4;                                     \
        uint32_t full = sbase + MB_FULL(S);                                     \
        uint32_t dst  = sbase + SMEM_STAGE0 + (S) * STAGE_BYTES;                \
        MBARRIER_EXPECT_TX(full, STAGE_BYTES);                                  \
        BULK_G2S(dst, Asrc0 + (size_t)knext * (M_DIM * BK),                     \
                 A_STAGE_BYTES, full);                                          \
        BULK_G2S(dst + A_STAGE_BYTES, Bsrc0 + (size_t)knext * (N_DIM * BK),     \
                 B_STAGE_BYTES, full);                                          \
    }                                                                           \
} while (0)

// ============================================================================
// fp16 GEMM: out[b,m,s] = sum_k W[m,k]*X[n,k] + bias[s],  n = b*2048 + s
// CTA tile 256x128; 16 warps (4 per SMSP), warp0-lane0 doubles as producer.
// ============================================================================
__global__ void __launch_bounds__(THREADS, 1) gemm_kernel(
    const float* __restrict__ bias, float* __restrict__ out)
{
    extern __shared__ uint32_t smem[];
    const uint32_t sbase = smem_u32(smem);

    const int tid  = threadIdx.x;
    const int wid  = tid >> 5;
    const int lane = tid & 31;

    // CTA tile mapping: bid = mt + 16*nt (wave covers all 16 m-tiles -> A reuse)
    const int mt = blockIdx.x & 15;
    const int nt = blockIdx.x >> 4;
    const int m0 = mt * BM;
    const int n0 = nt * BN;

    const __half* Asrc0 = g_Wh + (size_t)m0 * BK;
    const __half* Bsrc0 = g_Xh + (size_t)n0 * BK;

    if (tid == 0) {
        #pragma unroll
        for (int s = 0; s < STAGES; s++) {
            MBARRIER_INIT(sbase + MB_FULL(s), 1);
            MBARRIER_INIT(sbase + MB_EMPTY(s), 16);
        }
    }
    __syncthreads();

    // Prologue: fill all 4 stages (k = 0..3)
    if (tid == 0) {
        #pragma unroll
        for (int s = 0; s < STAGES; s++) {
            uint32_t full = sbase + MB_FULL(s);
            uint32_t dst  = sbase + SMEM_STAGE0 + s * STAGE_BYTES;
            MBARRIER_EXPECT_TX(full, STAGE_BYTES);
            BULK_G2S(dst, Asrc0 + (size_t)s * (M_DIM * BK), A_STAGE_BYTES, full);
            BULK_G2S(dst + A_STAGE_BYTES, Bsrc0 + (size_t)s * (N_DIM * BK),
                     B_STAGE_BYTES, full);
        }
    }

    // ------------------------- Fragment addressing -------------------------
    const int wm = wid & 3;         // warp m index 0..3 (64 rows each)
    const int wn = wid >> 2;        // warp n index 0..3 (32 rows each)
    const int l7 = lane & 7;        // XOR key == (stage row & 7) for all tiles

    // A ldmatrix lane row: lanes 0-15 -> rows 0-15 (k-lo), 16-31 -> rows (k-hi)
    const int rA = lane & 15;
    const int hA = lane >> 4;
    // B ldmatrix lane row: 0-7/8-15 -> rows of ni (k-lo/k-hi); 16-31 -> ni+1
    const int rB = (lane & 7) + ((lane & 16) >> 1);
    const int hB = (lane >> 3) & 1;

    uint32_t aAddr[4], bAddr[4];
    #pragma unroll
    for (int ks = 0; ks < 4; ks++) {
        aAddr[ks] = sbase + SMEM_STAGE0
                  + (uint32_t)((wm * 64 + rA) * 128)
                  + (uint32_t)(((2 * ks + hA) ^ l7) << 4);
        bAddr[ks] = sbase + SMEM_STAGE0 + A_STAGE_BYTES
                  + (uint32_t)((wn * 32 + rB) * 128)
                  + (uint32_t)(((2 * ks + hB) ^ l7) << 4);
    }

    float acc[4][4][4];
#pragma unroll
    for (int i = 0; i < 4; i++)
#pragma unroll
        for (int j = 0; j < 4; j++)
#pragma unroll
            for (int r = 0; r < 4; r++) acc[i][j][r] = 0.0f;

    for (int ko = 0; ko < K_OUTER; ko++) {
        const int ph = ko & 1;
        CONSUME_STAGE(0);
        CONSUME_STAGE(1);
        CONSUME_STAGE(2);
        CONSUME_STAGE(3);
    }

    // ------------------------------------------------------------------------
    // Epilogue: out[b, m, s] = acc + bias[s]; CTA tile lies in one batch
    // m16n8k16 accum: c0,c1 -> row g cols 2t,2t+1; c2,c3 -> row g+8
    // ------------------------------------------------------------------------
    const int g = lane >> 2;
    const int t = lane & 3;
    const int b   = n0 >> 11;        // n0 / 2048
    const int s0c = n0 & 2047;
    float* obase = out + (size_t)b * M_DIM * S_DIM;

#pragma unroll
    for (int mi = 0; mi < 4; mi++) {
#pragma unroll
        for (int ni = 0; ni < 4; ni++) {
            int sl = s0c + wn * 32 + ni * 8 + 2 * t;
            float2 bv = *reinterpret_cast<const float2*>(bias + sl);
            int m = m0 + wm * 64 + mi * 16 + g;

            float2 v0;
            v0.x = acc[mi][ni][0] + bv.x;
            v0.y = acc[mi][ni][1] + bv.y;
            *reinterpret_cast<float2*>(obase + (size_t)m * S_DIM + sl) = v0;

            float2 v1;
            v1.x = acc[mi][ni][2] + bv.x;
            v1.y = acc[mi][ni][3] + bv.y;
            *reinterpret_cast<float2*>(obase + (size_t)(m + 8) * S_DIM + sl) = v1;
        }
    }
}

// ============================================================================
// Host launch — conv_x forked onto a side stream (graph-capture branch) so it
// overlaps the memset+scatter chain; join before the GEMM.
// ============================================================================
extern "C" void kernel_launch(void* const* d_in, const int* in_sizes, int n_in,
                              void* d_out, int out_size) {
    const float* x      = (const float*)d_in[0];
    const float* values = (const float*)d_in[1];
    const float* bias   = (const float*)d_in[2];
    const int* row_ids  = (const int*)d_in[3];
    const int* col_idx  = (const int*)d_in[4];
    int nnz = in_sizes[1];
    float* out = (float*)d_out;

    // One-time resources (created on the uncaptured correctness call).
    static cudaStream_t s2 = nullptr;
    static cudaEvent_t ev_fork = nullptr, ev_join = nullptr;
    static bool attr_set = false;
    if (!attr_set) {
        cudaStreamCreateWithFlags(&s2, cudaStreamNonBlocking);
        cudaEventCreateWithFlags(&ev_fork, cudaEventDisableTiming);
        cudaEventCreateWithFlags(&ev_join, cudaEventDisableTiming);
        cudaFuncSetAttribute(gemm_kernel,
                             cudaFuncAttributeMaxDynamicSharedMemorySize,
                             SMEM_BYTES);
        attr_set = true;
    }

    void* whptr = nullptr;
    cudaGetSymbolAddress(&whptr, g_Wh);

    // ---- branch: conv_x depends only on input x ----
    cudaEventRecord(ev_fork, 0);
    cudaStreamWaitEvent(s2, ev_fork, 0);
    conv_x_kernel<<<(N_DIM * (K_DIM / 8) + 255) / 256, 256, 0, s2>>>(x);
    cudaEventRecord(ev_join, s2);

    // ---- main chain: zero fp16 W, scatter-add in fp16 blocked layout ----
    cudaMemsetAsync(whptr, 0, (size_t)M_DIM * K_DIM * sizeof(__half));
    scatter_kernel<<<(nnz + 255) / 256, 256>>>(values, row_ids, col_idx, nnz);

    // ---- join, then GEMM ----
    cudaStreamWaitEvent(0, ev_join, 0);
    gemm_kernel<<<(M_DIM / BM) * (N_DIM / BN), THREADS, SMEM_BYTES>>>(bias, out);
}

// round 16
// speedup vs baseline: 2.9664x; 1.0387x over previous
#include <cuda_runtime.h>
#include <cuda_fp16.h>
#include <cstdint>

// ============================================================================
// Problem constants
// ============================================================================
#define M_DIM 4096
#define K_DIM 4096
#define S_DIM 2048
#define N_DIM 16384            // B*S = 8*2048

#define BM 256
#define BN 128
#define BK 64                  // fp16: 64 k-elems = 128B per row chunk
#define K_ITERS (K_DIM / BK)   // 64
#define STAGES 4
#define K_OUTER (K_ITERS / STAGES)   // 16

#define THREADS 256            // 8 warps (4m x 2n, warp tile 64x64); warp0-lane0 produces

// Stage: A 256x64 fp16 (32KB) + B 128x64 fp16 (16KB), packed 128B/row
#define A_STAGE_BYTES 32768
#define B_STAGE_BYTES 16384
#define STAGE_BYTES   (A_STAGE_BYTES + B_STAGE_BYTES)   // 49152
#define SMEM_STAGE0   1024
#define SMEM_BYTES    (SMEM_STAGE0 + STAGES * STAGE_BYTES)  // 197632

// mbarriers: full[s] at s*16, empty[s] at s*16+8
#define MB_FULL(s)  ((s) * 16)
#define MB_EMPTY(s) ((s) * 16 + 8)

// ============================================================================
// Scratch (device globals)
//
// g_Wh/g_Xh: fp16 blocked [kb][row][64]  (kb = k/64, chunk = 128B row).
// Within a 64-half chunk, logical k index j (0..63) stored at half index:
//   l = j>>3 (16B granule 0..7), stored granule = l ^ (row & 7)
//   half_idx = (l ^ (row&7))*8 + (j&7)
// => ldmatrix tiles (8 consecutive rows x one logical granule) hit 8 distinct
//    stored granules -> conflict-free.
// g_Wh is ALSO the scatter-add target (fp16 atomics, blocked address).
// ============================================================================
__device__ __align__(128) __half g_Wh[(size_t)M_DIM * K_DIM];   // 32 MB
__device__ __align__(128) __half g_Xh[(size_t)N_DIM * K_DIM];   // 128 MB

// ============================================================================
// Helpers
// ============================================================================
__device__ __forceinline__ uint32_t smem_u32(const void* p) {
    uint32_t a;
    asm("{ .reg .u64 t; cvta.to.shared.u64 t, %1; cvt.u32.u64 %0, t; }"
        : "=r"(a) : "l"(p));
    return a;
}

// ldmatrix x4 with compile-time immediate offset.
template <int IMM>
__device__ __forceinline__ void ldsm_x4(uint32_t* r, uint32_t addr) {
    asm volatile("ldmatrix.sync.aligned.m8n8.x4.shared.b16 {%0,%1,%2,%3}, [%4+%5];"
                 : "=r"(r[0]), "=r"(r[1]), "=r"(r[2]), "=r"(r[3])
                 : "r"(addr), "n"(IMM));
}

// m16n8k16 fp16 MMA, fp32 accumulate.
__device__ __forceinline__ void mma_f16(float* c,
                                        uint32_t a0, uint32_t a1,
                                        uint32_t a2, uint32_t a3,
                                        uint32_t b0, uint32_t b1) {
    asm volatile(
        "mma.sync.aligned.m16n8k16.row.col.f32.f16.f16.f32 "
        "{%0,%1,%2,%3}, {%4,%5,%6,%7}, {%8,%9}, {%0,%1,%2,%3};"
        : "+f"(c[0]), "+f"(c[1]), "+f"(c[2]), "+f"(c[3])
        : "r"(a0), "r"(a1), "r"(a2), "r"(a3), "r"(b0), "r"(b1));
}

#define MBARRIER_INIT(mbar, count) \
    asm volatile("mbarrier.init.shared.b64 [%0], %1;" \
                 :: "r"((uint32_t)(mbar)), "r"((uint32_t)(count)) : "memory")

#define MBARRIER_ARRIVE(mbar) \
    asm volatile("mbarrier.arrive.shared.b64 _, [%0];" \
                 :: "r"((uint32_t)(mbar)) : "memory")

#define MBARRIER_EXPECT_TX(mbar, tx_bytes) \
    asm volatile("mbarrier.arrive.expect_tx.shared.b64 _, [%0], %1;" \
                 :: "r"((uint32_t)(mbar)), "r"((uint32_t)(tx_bytes)) : "memory")

#define MBARRIER_WAIT_PARITY(mbar, parity) do {                                   \
    uint32_t _mbar = (uint32_t)(mbar);                                            \
    uint32_t _par = (uint32_t)(parity);                                           \
    uint32_t _done;                                                               \
    asm volatile(                                                                 \
        "{\n\t.reg .pred p;\n\t"                                                  \
        "mbarrier.try_wait.parity.acquire.cta.shared::cta.b64 p, [%1], %2;\n\t"   \
        "selp.b32 %0, 1, 0, p;\n\t}"                                              \
        : "=r"(_done) : "r"(_mbar), "r"(_par) : "memory");                        \
    if (!_done) {                                                                 \
        asm volatile(                                                             \
            "{\n\t.reg .pred P1;\n\t"                                             \
            "WAIT_LOOP_%=:\n\t"                                                   \
            "mbarrier.try_wait.parity.acquire.cta.shared::cta.b64 P1, [%0], %1, 0x989680;\n\t" \
            "@P1 bra.uni WAIT_DONE_%=;\n\t"                                       \
            "bra.uni WAIT_LOOP_%=;\n\t"                                           \
            "WAIT_DONE_%=:\n\t}"                                                  \
            :: "r"(_mbar), "r"(_par) : "memory");                                 \
    }                                                                             \
} while (0)

#define MBARRIER_WAIT_PARITY_RELAXED(mbar, parity) do {                           \
    uint32_t _mbar = (uint32_t)(mbar);                                            \
    uint32_t _par = (uint32_t)(parity);                                           \
    uint32_t _done;                                                               \
    asm volatile(                                                                 \
        "{\n\t.reg .pred p;\n\t"                                                  \
        "mbarrier.try_wait.parity.relaxed.cta.shared::cta.b64 p, [%1], %2, 0x989680;\n\t" \
        "selp.b32 %0, 1, 0, p;\n\t}"                                              \
        : "=r"(_done) : "r"(_mbar), "r"(_par) : "memory");                        \
    if (!_done) {                                                                 \
        asm volatile(                                                             \
            "{\n\t.reg .pred P1;\n\t"                                             \
            "WAIT_LOOP_%=:\n\t"                                                   \
            "mbarrier.try_wait.parity.relaxed.cta.shared::cta.b64 P1, [%0], %1, 0x989680;\n\t" \
            "@P1 bra.uni WAIT_DONE_%=;\n\t"                                       \
            "bra.uni WAIT_LOOP_%=;\n\t"                                           \
            "WAIT_DONE_%=:\n\t}"                                                  \
            :: "r"(_mbar), "r"(_par) : "memory");                                 \
    }                                                                             \
} while (0)

#define BULK_G2S(dst_smem, src_gmem, nbytes, mbar)                                \
    asm volatile(                                                                 \
        "cp.async.bulk.shared::cta.global.mbarrier::complete_tx::bytes "          \
        "[%0], [%1], %2, [%3];"                                                   \
        :: "r"((uint32_t)(dst_smem)), "l"(src_gmem),                              \
           "r"((uint32_t)(nbytes)), "r"((uint32_t)(mbar)) : "memory")

// ============================================================================
// Pre-pass kernels (identical to validated R15)
// ============================================================================

// COO scatter-add DIRECTLY into the fp16 blocked+XOR layout.
__global__ void scatter_kernel(const float* __restrict__ vals,
                               const int* __restrict__ rows,
                               const int* __restrict__ cols, int nnz) {
    int i = blockIdx.x * blockDim.x + threadIdx.x;
    if (i < nnz) {
        int r  = rows[i], c = cols[i];
        int kb = c >> 6;                 // BK = 64
        int j  = c & 63;
        int l  = j >> 3;
        int g  = l ^ (r & 7);
        size_t off = (size_t)kb * (M_DIM * BK) + (size_t)r * BK + g * 8 + (j & 7);
        atomicAdd(&g_Wh[off], __float2half(vals[i]));
    }
}

// Convert 8 fp32 -> one 16B fp16 granule (register-only, no local memory).
__device__ __forceinline__ uint4 cvt8(const float4* s) {
    float4 f0 = s[0];
    float4 f1 = s[1];
    __half2 h0 = __float22half2_rn(make_float2(f0.x, f0.y));
    __half2 h1 = __float22half2_rn(make_float2(f0.z, f0.w));
    __half2 h2 = __float22half2_rn(make_float2(f1.x, f1.y));
    __half2 h3 = __float22half2_rn(make_float2(f1.z, f1.w));
    uint4 o;
    o.x = *reinterpret_cast<uint32_t*>(&h0);
    o.y = *reinterpret_cast<uint32_t*>(&h1);
    o.z = *reinterpret_cast<uint32_t*>(&h2);
    o.w = *reinterpret_cast<uint32_t*>(&h3);
    return o;
}

// x (fp32 natural) -> g_Xh (fp16 blocked + granule-XOR). One thread/granule.
__global__ void conv_x_kernel(const float* __restrict__ x) {
    int idx = blockIdx.x * blockDim.x + threadIdx.x;      // N*K/8 = 8388608
    if (idx >= N_DIM * (K_DIM / 8)) return;
    int g   = idx & 7;
    int n   = (idx >> 3) & (N_DIM - 1);
    int kb  = idx >> (3 + 14);                            // / (8 * N_DIM)
    int l   = g ^ (n & 7);
    const float4* src = reinterpret_cast<const float4*>(
        x + (size_t)n * K_DIM + kb * BK + l * 8);
    uint4* dst = reinterpret_cast<uint4*>(
        g_Xh + (size_t)kb * (N_DIM * BK) + (size_t)n * BK + g * 8);
    *dst = cvt8(src);
}

// ============================================================================
// Mainloop: warp tile 64(m) x 64(n), m16n8k16, 4 ksteps (K=16) per k-iter.
// Per kstep: 4 A ldmatrix.x4 (one per mi) + 4 B ldmatrix.x4 (2 ni each),
// 32 MMAs. Stage & mi/ni offsets are literal immediates on LDSM.
// ============================================================================
#define KSTEP(S, KS) do {                                                       \
    uint32_t a[4][4], bb[16];                                                   \
    ldsm_x4<(S)*STAGE_BYTES +    0>(a[0], aAddr[KS]);                           \
    ldsm_x4<(S)*STAGE_BYTES + 2048>(a[1], aAddr[KS]);                           \
    ldsm_x4<(S)*STAGE_BYTES + 4096>(a[2], aAddr[KS]);                           \
    ldsm_x4<(S)*STAGE_BYTES + 6144>(a[3], aAddr[KS]);                           \
    ldsm_x4<(S)*STAGE_BYTES +    0>(bb,      bAddr[KS]);                        \
    ldsm_x4<(S)*STAGE_BYTES + 2048>(bb +  4, bAddr[KS]);                        \
    ldsm_x4<(S)*STAGE_BYTES + 4096>(bb +  8, bAddr[KS]);                        \
    ldsm_x4<(S)*STAGE_BYTES + 6144>(bb + 12, bAddr[KS]);                        \
    _Pragma("unroll")                                                           \
    for (int ni = 0; ni < 8; ni++) {                                            \
        _Pragma("unroll")                                                       \
        for (int mi = 0; mi < 4; mi++) {                                        \
            mma_f16(acc[mi][ni], a[mi][0], a[mi][1], a[mi][2], a[mi][3],        \
                    bb[ni * 2], bb[ni * 2 + 1]);                                \
        }                                                                       \
    }                                                                           \
} while (0)

#define CONSUME_STAGE(S) do {                                                   \
    MBARRIER_WAIT_PARITY(sbase + MB_FULL(S), ph);                               \
    KSTEP(S, 0); KSTEP(S, 1); KSTEP(S, 2); KSTEP(S, 3);                         \
    __syncwarp();                                                               \
    if (lane == 0) MBARRIER_ARRIVE(sbase + MB_EMPTY(S));                        \
    if (tid == 0 && ko < K_OUTER - 1) {                                         \
        /* refill this slot with k-iter (4*ko + S + 4) */                       \
        MBARRIER_WAIT_PARITY_RELAXED(sbase + MB_EMPTY(S), ph);                  \
        const int knext = 4 * ko + (S) + 4;                                     \
        uint32_t full = sbase + MB_FULL(S);                                     \
        uint32_t dst  = sbase + SMEM_STAGE0 + (S) * STAGE_BYTES;                \
        MBARRIER_EXPECT_TX(full, STAGE_BYTES);                                  \
        BULK_G2S(dst, Asrc0 + (size_t)knext * (M_DIM * BK),                     \
                 A_STAGE_BYTES, full);                                          \
        BULK_G2S(dst + A_STAGE_BYTES, Bsrc0 + (size_t)knext * (N_DIM * BK),     \
                 B_STAGE_BYTES, full);                                          \
    }                                                                           \
} while (0)

// ============================================================================
// fp16 GEMM: out[b,m,s] = sum_k W[m,k]*X[n,k] + bias[s],  n = b*2048 + s
// CTA tile 256x128; 8 warps (2 per SMSP), warp0-lane0 doubles as producer.
// ============================================================================
__global__ void __launch_bounds__(THREADS, 1) gemm_kernel(
    const float* __restrict__ bias, float* __restrict__ out)
{
    extern __shared__ uint32_t smem[];
    const uint32_t sbase = smem_u32(smem);

    const int tid  = threadIdx.x;
    const int wid  = tid >> 5;
    const int lane = tid & 31;

    // CTA tile mapping: bid = mt + 16*nt (wave covers all 16 m-tiles -> A reuse)
    const int mt = blockIdx.x & 15;
    const int nt = blockIdx.x >> 4;
    const int m0 = mt * BM;
    const int n0 = nt * BN;

    const __half* Asrc0 = g_Wh + (size_t)m0 * BK;
    const __half* Bsrc0 = g_Xh + (size_t)n0 * BK;

    if (tid == 0) {
        #pragma unroll
        for (int s = 0; s < STAGES; s++) {
            MBARRIER_INIT(sbase + MB_FULL(s), 1);
            MBARRIER_INIT(sbase + MB_EMPTY(s), 8);
        }
    }
    __syncthreads();

    // Prologue: fill all 4 stages (k = 0..3)
    if (tid == 0) {
        #pragma unroll
        for (int s = 0; s < STAGES; s++) {
            uint32_t full = sbase + MB_FULL(s);
            uint32_t dst  = sbase + SMEM_STAGE0 + s * STAGE_BYTES;
            MBARRIER_EXPECT_TX(full, STAGE_BYTES);
            BULK_G2S(dst, Asrc0 + (size_t)s * (M_DIM * BK), A_STAGE_BYTES, full);
            BULK_G2S(dst + A_STAGE_BYTES, Bsrc0 + (size_t)s * (N_DIM * BK),
                     B_STAGE_BYTES, full);
        }
    }

    // ------------------------- Fragment addressing -------------------------
    const int wm = wid & 3;         // warp m index 0..3 (64 rows each)
    const int wn = wid >> 2;        // warp n index 0..1 (64 rows each)
    const int l7 = lane & 7;        // XOR key == (stage row & 7) for all tiles

    // A ldmatrix lane row: lanes 0-15 -> rows 0-15 (k-lo), 16-31 -> rows (k-hi)
    const int rA = lane & 15;
    const int hA = lane >> 4;
    // B ldmatrix lane row: 0-7/8-15 -> rows of ni (k-lo/k-hi); 16-31 -> ni+1
    const int rB = (lane & 7) + ((lane & 16) >> 1);
    const int hB = (lane >> 3) & 1;

    uint32_t aAddr[4], bAddr[4];
    #pragma unroll
    for (int ks = 0; ks < 4; ks++) {
        aAddr[ks] = sbase + SMEM_STAGE0
                  + (uint32_t)((wm * 64 + rA) * 128)
                  + (uint32_t)(((2 * ks + hA) ^ l7) << 4);
        bAddr[ks] = sbase + SMEM_STAGE0 + A_STAGE_BYTES
                  + (uint32_t)((wn * 64 + rB) * 128)
                  + (uint32_t)(((2 * ks + hB) ^ l7) << 4);
    }

    float acc[4][8][4];
#pragma unroll
    for (int i = 0; i < 4; i++)
#pragma unroll
        for (int j = 0; j < 8; j++)
#pragma unroll
            for (int r = 0; r < 4; r++) acc[i][j][r] = 0.0f;

    for (int ko = 0; ko < K_OUTER; ko++) {
        const int ph = ko & 1;
        CONSUME_STAGE(0);
        CONSUME_STAGE(1);
        CONSUME_STAGE(2);
        CONSUME_STAGE(3);
    }

    // ------------------------------------------------------------------------
    // Epilogue: out[b, m, s] = acc + bias[s]; CTA tile lies in one batch
    // m16n8k16 accum: c0,c1 -> row g cols 2t,2t+1; c2,c3 -> row g+8
    // ------------------------------------------------------------------------
    const int g = lane >> 2;
    const int t = lane & 3;
    const int b   = n0 >> 11;        // n0 / 2048
    const int s0c = n0 & 2047;
    float* obase = out + (size_t)b * M_DIM * S_DIM;

#pragma unroll
    for (int mi = 0; mi < 4; mi++) {
#pragma unroll
        for (int ni = 0; ni < 8; ni++) {
            int sl = s0c + wn * 64 + ni * 8 + 2 * t;
            float2 bv = *reinterpret_cast<const float2*>(bias + sl);
            int m = m0 + wm * 64 + mi * 16 + g;

            float2 v0;
            v0.x = acc[mi][ni][0] + bv.x;
            v0.y = acc[mi][ni][1] + bv.y;
            *reinterpret_cast<float2*>(obase + (size_t)m * S_DIM + sl) = v0;

            float2 v1;
            v1.x = acc[mi][ni][2] + bv.x;
            v1.y = acc[mi][ni][3] + bv.y;
            *reinterpret_cast<float2*>(obase + (size_t)(m + 8) * S_DIM + sl) = v1;
        }
    }
}

// ============================================================================
// Host launch — conv_x forked onto a side stream (graph-capture branch) so it
// overlaps the memset+scatter chain; join before the GEMM.
// ============================================================================
extern "C" void kernel_launch(void* const* d_in, const int* in_sizes, int n_in,
                              void* d_out, int out_size) {
    const float* x      = (const float*)d_in[0];
    const float* values = (const float*)d_in[1];
    const float* bias   = (const float*)d_in[2];
    const int* row_ids  = (const int*)d_in[3];
    const int* col_idx  = (const int*)d_in[4];
    int nnz = in_sizes[1];
    float* out = (float*)d_out;

    // One-time resources (created on the uncaptured correctness call).
    static cudaStream_t s2 = nullptr;
    static cudaEvent_t ev_fork = nullptr, ev_join = nullptr;
    static bool attr_set = false;
    if (!attr_set) {
        cudaStreamCreateWithFlags(&s2, cudaStreamNonBlocking);
        cudaEventCreateWithFlags(&ev_fork, cudaEventDisableTiming);
        cudaEventCreateWithFlags(&ev_join, cudaEventDisableTiming);
        cudaFuncSetAttribute(gemm_kernel,
                             cudaFuncAttributeMaxDynamicSharedMemorySize,
                             SMEM_BYTES);
        attr_set = true;
    }

    void* whptr = nullptr;
    cudaGetSymbolAddress(&whptr, g_Wh);

    // ---- branch: conv_x depends only on input x ----
    cudaEventRecord(ev_fork, 0);
    cudaStreamWaitEvent(s2, ev_fork, 0);
    conv_x_kernel<<<(N_DIM * (K_DIM / 8) + 255) / 256, 256, 0, s2>>>(x);
    cudaEventRecord(ev_join, s2);

    // ---- main chain: zero fp16 W, scatter-add in fp16 blocked layout ----
    cudaMemsetAsync(whptr, 0, (size_t)M_DIM * K_DIM * sizeof(__half));
    scatter_kernel<<<(nnz + 255) / 256, 256>>>(values, row_ids, col_idx, nnz);

    // ---- join, then GEMM ----
    cudaStreamWaitEvent(0, ev_join, 0);
    gemm_kernel<<<(M_DIM / BM) * (N_DIM / BN), THREADS, SMEM_BYTES>>>(bias, out);
}